// round 1
// baseline (speedup 1.0000x reference)
#include <cuda_runtime.h>
#include <math.h>

// Problem constants
#define N_ROWS  32768
#define D_DIM   512
#define K_CODES 2048
#define HALFW   256

// Output layout: [loss(1) | q_out(2*32768*256) | perplexity(1) | encodings(32768*2048)]
#define OFF_QOUT 1
#define OFF_PERP (1 + N_ROWS * D_DIM)              // 16777217
#define OFF_ENC  (2 + N_ROWS * D_DIM)              // 16777218

// Scratch (device globals: allocation-free per harness rules)
__device__ float g_h[(size_t)N_ROWS * D_DIM];      // 64 MB
__device__ float g_en[K_CODES];                    // ||e_k||^2
__device__ int   g_idx[N_ROWS];
__device__ float g_partial[N_ROWS];
__device__ int   g_counts[K_CODES];

// ---------------------------------------------------------------------------
// GEMM1: g_h = concat(x0,x1) @ W^T + b      (NT GEMM, fp32)
// BM=128, BN=128, BK=16, 256 threads, 8x8 microtile
// ---------------------------------------------------------------------------
__global__ __launch_bounds__(256, 2)
void gemm1_kernel(const float* __restrict__ x0, const float* __restrict__ x1,
                  const float* __restrict__ W, const float* __restrict__ bias)
{
    __shared__ float As[16][128];
    __shared__ float Bs[16][128];
    const int m0  = blockIdx.y * 128;
    const int n0  = blockIdx.x * 128;
    const int tid = threadIdx.x;
    const int tx  = tid & 15, ty = tid >> 4;

    float acc[8][8];
#pragma unroll
    for (int i = 0; i < 8; i++)
#pragma unroll
        for (int j = 0; j < 8; j++) acc[i][j] = 0.0f;

    for (int kt = 0; kt < D_DIM; kt += 16) {
        // A tile: concat(x0,x1); BK=16 tile never crosses the 256-col boundary
        const float* Asrc = (kt < HALFW) ? x0 : x1;
        const int    kc   = (kt < HALFW) ? kt : (kt - HALFW);
#pragma unroll
        for (int r = 0; r < 2; r++) {
            int q   = tid + r * 256;     // float4 index 0..511
            int row = q >> 2;
            int c4  = (q & 3) << 2;
            float4 v = *(const float4*)(Asrc + (size_t)(m0 + row) * HALFW + kc + c4);
            As[c4 + 0][row] = v.x; As[c4 + 1][row] = v.y;
            As[c4 + 2][row] = v.z; As[c4 + 3][row] = v.w;
        }
#pragma unroll
        for (int r = 0; r < 2; r++) {
            int q   = tid + r * 256;
            int row = q >> 2;
            int c4  = (q & 3) << 2;
            float4 v = *(const float4*)(W + (size_t)(n0 + row) * D_DIM + kt + c4);
            Bs[c4 + 0][row] = v.x; Bs[c4 + 1][row] = v.y;
            Bs[c4 + 2][row] = v.z; Bs[c4 + 3][row] = v.w;
        }
        __syncthreads();
#pragma unroll
        for (int kk = 0; kk < 16; kk++) {
            float a[8], b[8];
#pragma unroll
            for (int i = 0; i < 8; i++) a[i] = As[kk][ty * 8 + i];
#pragma unroll
            for (int j = 0; j < 8; j++) b[j] = Bs[kk][tx * 8 + j];
#pragma unroll
            for (int i = 0; i < 8; i++)
#pragma unroll
                for (int j = 0; j < 8; j++)
                    acc[i][j] += a[i] * b[j];
        }
        __syncthreads();
    }
#pragma unroll
    for (int i = 0; i < 8; i++) {
        int row = m0 + ty * 8 + i;
#pragma unroll
        for (int j = 0; j < 8; j += 4) {
            int col = n0 + tx * 8 + j;
            float4 v;
            v.x = acc[i][j + 0] + bias[col + 0];
            v.y = acc[i][j + 1] + bias[col + 1];
            v.z = acc[i][j + 2] + bias[col + 2];
            v.w = acc[i][j + 3] + bias[col + 3];
            *(float4*)(g_h + (size_t)row * D_DIM + col) = v;
        }
    }
}

// ---------------------------------------------------------------------------
// ||e_k||^2 + zero counts
// ---------------------------------------------------------------------------
__global__ void en_kernel(const float* __restrict__ emb)
{
    __shared__ float red[128];
    const int k   = blockIdx.x;
    const int tid = threadIdx.x;
    float4 v = *(const float4*)(emb + (size_t)k * D_DIM + tid * 4);
    red[tid] = v.x * v.x + v.y * v.y + v.z * v.z + v.w * v.w;
    __syncthreads();
    for (int off = 64; off; off >>= 1) {
        if (tid < off) red[tid] += red[tid + off];
        __syncthreads();
    }
    if (tid == 0) { g_en[k] = red[0]; g_counts[k] = 0; }
}

// ---------------------------------------------------------------------------
// GEMM2 fused argmin: per 128-row block, stream all 2048 codes,
// track argmin_k (||e_k||^2 - 2 h.e_k). Scores never hit memory.
// ---------------------------------------------------------------------------
__global__ __launch_bounds__(256, 2)
void gemm2_argmin_kernel(const float* __restrict__ emb)
{
    __shared__ float As[16][128];
    __shared__ float Bs[16][128];
    const int m0  = blockIdx.x * 128;
    const int tid = threadIdx.x;
    const int tx  = tid & 15, ty = tid >> 4;

    float minv[8];
    int   mini[8];
#pragma unroll
    for (int i = 0; i < 8; i++) { minv[i] = 3.4e38f; mini[i] = 0; }

    for (int nt = 0; nt < K_CODES / 128; nt++) {
        const int n0 = nt * 128;
        float acc[8][8];
#pragma unroll
        for (int i = 0; i < 8; i++)
#pragma unroll
            for (int j = 0; j < 8; j++) acc[i][j] = 0.0f;

        for (int kt = 0; kt < D_DIM; kt += 16) {
#pragma unroll
            for (int r = 0; r < 2; r++) {
                int q   = tid + r * 256;
                int row = q >> 2;
                int c4  = (q & 3) << 2;
                float4 v = *(const float4*)(g_h + (size_t)(m0 + row) * D_DIM + kt + c4);
                As[c4 + 0][row] = v.x; As[c4 + 1][row] = v.y;
                As[c4 + 2][row] = v.z; As[c4 + 3][row] = v.w;
            }
#pragma unroll
            for (int r = 0; r < 2; r++) {
                int q   = tid + r * 256;
                int row = q >> 2;
                int c4  = (q & 3) << 2;
                float4 v = *(const float4*)(emb + (size_t)(n0 + row) * D_DIM + kt + c4);
                Bs[c4 + 0][row] = v.x; Bs[c4 + 1][row] = v.y;
                Bs[c4 + 2][row] = v.z; Bs[c4 + 3][row] = v.w;
            }
            __syncthreads();
#pragma unroll
            for (int kk = 0; kk < 16; kk++) {
                float a[8], b[8];
#pragma unroll
                for (int i = 0; i < 8; i++) a[i] = As[kk][ty * 8 + i];
#pragma unroll
                for (int j = 0; j < 8; j++) b[j] = Bs[kk][tx * 8 + j];
#pragma unroll
                for (int i = 0; i < 8; i++)
#pragma unroll
                    for (int j = 0; j < 8; j++)
                        acc[i][j] += a[i] * b[j];
            }
            __syncthreads();
        }
        float env[8];
#pragma unroll
        for (int j = 0; j < 8; j++) env[j] = g_en[n0 + tx * 8 + j];
#pragma unroll
        for (int i = 0; i < 8; i++)
#pragma unroll
            for (int j = 0; j < 8; j++) {
                float s = env[j] - 2.0f * acc[i][j];
                int col = n0 + tx * 8 + j;
                if (s < minv[i]) { minv[i] = s; mini[i] = col; }  // strict <: keeps first min
            }
    }

    // reduce across the 16 tx-lanes sharing the same rows (lanes 0-15 / 16-31)
#pragma unroll
    for (int off = 8; off; off >>= 1) {
#pragma unroll
        for (int i = 0; i < 8; i++) {
            float ov = __shfl_xor_sync(0xffffffffu, minv[i], off);
            int   oi = __shfl_xor_sync(0xffffffffu, mini[i], off);
            if (ov < minv[i] || (ov == minv[i] && oi < mini[i])) { minv[i] = ov; mini[i] = oi; }
        }
    }
    if (tx == 0) {
#pragma unroll
        for (int i = 0; i < 8; i++) g_idx[m0 + ty * 8 + i] = mini[i];
    }
}

// ---------------------------------------------------------------------------
// Epilogue per row: q_out (STE == h + (q-h)), encodings row (zeros + one),
// per-row loss partial, count histogram (int atomics: deterministic).
// ---------------------------------------------------------------------------
__global__ void epilogue_kernel(const float* __restrict__ emb, float* __restrict__ out)
{
    __shared__ float red[128];
    const int n   = blockIdx.x;
    const int tid = threadIdx.x;
    const int idx = g_idx[n];

    float4 hv = *(const float4*)(g_h + (size_t)n * D_DIM + tid * 4);
    float4 qv = *(const float4*)(emb + (size_t)idx * D_DIM + tid * 4);
    float d0 = qv.x - hv.x, d1 = qv.y - hv.y, d2 = qv.z - hv.z, d3 = qv.w - hv.w;

    float* qo = out + OFF_QOUT + (size_t)n * D_DIM + tid * 4;   // misaligned base: scalar stores
    qo[0] = hv.x + d0; qo[1] = hv.y + d1; qo[2] = hv.z + d2; qo[3] = hv.w + d3;

    red[tid] = d0 * d0 + d1 * d1 + d2 * d2 + d3 * d3;

    // encodings row: zero + scatter one (float2-aligned region)
    float2* er2 = (float2*)(out + OFF_ENC + (size_t)n * K_CODES);
    const int unit = idx >> 1, comp = idx & 1;
#pragma unroll
    for (int i = 0; i < 8; i++) {
        int u = tid + i * 128;
        float2 v = make_float2(0.0f, 0.0f);
        if (u == unit) { if (comp == 0) v.x = 1.0f; else v.y = 1.0f; }
        er2[u] = v;
    }

    __syncthreads();
    for (int off = 64; off; off >>= 1) {
        if (tid < off) red[tid] += red[tid + off];
        __syncthreads();
    }
    if (tid == 0) {
        g_partial[n] = red[0];
        atomicAdd(&g_counts[idx], 1);
    }
}

// ---------------------------------------------------------------------------
// Final scalars: loss + perplexity (fixed-order reductions: deterministic)
// ---------------------------------------------------------------------------
__global__ void final_kernel(float* __restrict__ out)
{
    __shared__ float red[1024];
    const int tid = threadIdx.x;

    float s = 0.0f;
    for (int i = 0; i < N_ROWS / 1024; i++) s += g_partial[tid + i * 1024];
    red[tid] = s;
    __syncthreads();
    for (int off = 512; off; off >>= 1) {
        if (tid < off) red[tid] += red[tid + off];
        __syncthreads();
    }
    if (tid == 0) out[0] = 0.25f * red[0] / (float)((size_t)N_ROWS * D_DIM);
    __syncthreads();

    float p = 0.0f;
    for (int i = 0; i < K_CODES / 1024; i++) {
        float c  = (float)g_counts[tid + i * 1024];
        float pr = c * (1.0f / (float)N_ROWS);
        p += pr * logf(pr + 1e-10f);
    }
    red[tid] = p;
    __syncthreads();
    for (int off = 512; off; off >>= 1) {
        if (tid < off) red[tid] += red[tid + off];
        __syncthreads();
    }
    if (tid == 0) out[OFF_PERP] = expf(-red[0]);
}

// ---------------------------------------------------------------------------
extern "C" void kernel_launch(void* const* d_in, const int* in_sizes, int n_in,
                              void* d_out, int out_size)
{
    // Identify inputs by element count (robust to metadata ordering quirks)
    const float *x0 = nullptr, *x1 = nullptr, *W = nullptr, *b = nullptr, *emb = nullptr;
    for (int i = 0; i < n_in; i++) {
        const float* p = (const float*)d_in[i];
        const long long s = in_sizes[i];
        if (s == (long long)N_ROWS * HALFW)       { if (!x0) x0 = p; else x1 = p; }
        else if (s == (long long)D_DIM * D_DIM)   W = p;
        else if (s == (long long)D_DIM)           b = p;
        else if (s == (long long)K_CODES * D_DIM) emb = p;
    }
    float* out = (float*)d_out;

    gemm1_kernel<<<dim3(D_DIM / 128, N_ROWS / 128), 256>>>(x0, x1, W, b);
    en_kernel<<<K_CODES, 128>>>(emb);
    gemm2_argmin_kernel<<<N_ROWS / 128, 256>>>(emb);
    epilogue_kernel<<<N_ROWS, 128>>>(emb, out);
    final_kernel<<<1, 1024>>>(out);
}

// round 3
// speedup vs baseline: 1.5371x; 1.5371x over previous
#include <cuda_runtime.h>
#include <cuda_bf16.h>
#include <math.h>
#include <stdint.h>

// Problem constants
#define N_ROWS  32768
#define D_DIM   512
#define K_CODES 2048
#define HALFW   256

// Output layout: [loss(1) | q_out(2*32768*256) | perplexity(1) | encodings(32768*2048)]
#define OFF_QOUT 1
#define OFF_PERP (1 + N_ROWS * D_DIM)
#define OFF_ENC  (2 + N_ROWS * D_DIM)

#define MARGIN 0.05f

// Scratch (device globals: allocation-free per harness rules)
__device__ float         g_h[(size_t)N_ROWS * D_DIM];
__device__ __nv_bfloat16 g_hhi[(size_t)N_ROWS * D_DIM];
__device__ __nv_bfloat16 g_hlo[(size_t)N_ROWS * D_DIM];
__device__ __nv_bfloat16 g_ehi[(size_t)K_CODES * D_DIM];
__device__ __nv_bfloat16 g_elo[(size_t)K_CODES * D_DIM];
__device__ float g_en[K_CODES];
__device__ int   g_idx[N_ROWS];
__device__ float g_partial[N_ROWS];
__device__ int   g_counts[K_CODES];
__device__ int   g_nflag;
__device__ int   g_flagged[N_ROWS];

// ---------------------------------------------------------------------------
// mma.sync m16n8k16 bf16 (HMMA, works on base sm_100)
// ---------------------------------------------------------------------------
__device__ __forceinline__ void mma16816(float* c, const uint32_t* a, const uint32_t* b) {
    asm volatile(
        "mma.sync.aligned.m16n8k16.row.col.f32.bf16.bf16.f32 "
        "{%0,%1,%2,%3}, {%4,%5,%6,%7}, {%8,%9}, {%0,%1,%2,%3};"
        : "+f"(c[0]), "+f"(c[1]), "+f"(c[2]), "+f"(c[3])
        : "r"(a[0]), "r"(a[1]), "r"(a[2]), "r"(a[3]), "r"(b[0]), "r"(b[1]));
}

// ---------------------------------------------------------------------------
// GEMM1: g_h = concat(x0,x1) @ W^T + b      (NT GEMM, fp32 — exact h)
// ---------------------------------------------------------------------------
__global__ __launch_bounds__(256, 2)
void gemm1_kernel(const float* __restrict__ x0, const float* __restrict__ x1,
                  const float* __restrict__ W, const float* __restrict__ bias)
{
    __shared__ float As[16][128];
    __shared__ float Bs[16][128];
    const int m0  = blockIdx.y * 128;
    const int n0  = blockIdx.x * 128;
    const int tid = threadIdx.x;
    const int tx  = tid & 15, ty = tid >> 4;

    float acc[8][8];
#pragma unroll
    for (int i = 0; i < 8; i++)
#pragma unroll
        for (int j = 0; j < 8; j++) acc[i][j] = 0.0f;

    for (int kt = 0; kt < D_DIM; kt += 16) {
        const float* Asrc = (kt < HALFW) ? x0 : x1;
        const int    kc   = (kt < HALFW) ? kt : (kt - HALFW);
#pragma unroll
        for (int r = 0; r < 2; r++) {
            int q = tid + r * 256, row = q >> 2, c4 = (q & 3) << 2;
            float4 v = *(const float4*)(Asrc + (size_t)(m0 + row) * HALFW + kc + c4);
            As[c4 + 0][row] = v.x; As[c4 + 1][row] = v.y;
            As[c4 + 2][row] = v.z; As[c4 + 3][row] = v.w;
        }
#pragma unroll
        for (int r = 0; r < 2; r++) {
            int q = tid + r * 256, row = q >> 2, c4 = (q & 3) << 2;
            float4 v = *(const float4*)(W + (size_t)(n0 + row) * D_DIM + kt + c4);
            Bs[c4 + 0][row] = v.x; Bs[c4 + 1][row] = v.y;
            Bs[c4 + 2][row] = v.z; Bs[c4 + 3][row] = v.w;
        }
        __syncthreads();
#pragma unroll
        for (int kk = 0; kk < 16; kk++) {
            float a[8], b[8];
#pragma unroll
            for (int i = 0; i < 8; i++) a[i] = As[kk][ty * 8 + i];
#pragma unroll
            for (int j = 0; j < 8; j++) b[j] = Bs[kk][tx * 8 + j];
#pragma unroll
            for (int i = 0; i < 8; i++)
#pragma unroll
                for (int j = 0; j < 8; j++)
                    acc[i][j] += a[i] * b[j];
        }
        __syncthreads();
    }
#pragma unroll
    for (int i = 0; i < 8; i++) {
        int row = m0 + ty * 8 + i;
#pragma unroll
        for (int j = 0; j < 8; j += 4) {
            int col = n0 + tx * 8 + j;
            float4 v;
            v.x = acc[i][j + 0] + bias[col + 0];
            v.y = acc[i][j + 1] + bias[col + 1];
            v.z = acc[i][j + 2] + bias[col + 2];
            v.w = acc[i][j + 3] + bias[col + 3];
            *(float4*)(g_h + (size_t)row * D_DIM + col) = v;
        }
    }
}

// ---------------------------------------------------------------------------
// prep_emb: ||e_k||^2 (fp32 exact), e -> bf16 hi/lo split, zero counts/nflag
// ---------------------------------------------------------------------------
__global__ void prep_emb_kernel(const float* __restrict__ emb)
{
    __shared__ float red[128];
    const int k   = blockIdx.x;
    const int tid = threadIdx.x;
    const size_t base = (size_t)k * D_DIM + tid * 4;
    float4 v = *(const float4*)(emb + base);
    red[tid] = v.x * v.x + v.y * v.y + v.z * v.z + v.w * v.w;

    __nv_bfloat16 hx = __float2bfloat16_rn(v.x), hy = __float2bfloat16_rn(v.y);
    __nv_bfloat16 hz = __float2bfloat16_rn(v.z), hw = __float2bfloat16_rn(v.w);
    __nv_bfloat16 lx = __float2bfloat16_rn(v.x - __bfloat162float(hx));
    __nv_bfloat16 ly = __float2bfloat16_rn(v.y - __bfloat162float(hy));
    __nv_bfloat16 lz = __float2bfloat16_rn(v.z - __bfloat162float(hz));
    __nv_bfloat16 lw = __float2bfloat16_rn(v.w - __bfloat162float(hw));
    *(__nv_bfloat162*)(g_ehi + base)     = __nv_bfloat162(hx, hy);
    *(__nv_bfloat162*)(g_ehi + base + 2) = __nv_bfloat162(hz, hw);
    *(__nv_bfloat162*)(g_elo + base)     = __nv_bfloat162(lx, ly);
    *(__nv_bfloat162*)(g_elo + base + 2) = __nv_bfloat162(lz, lw);

    __syncthreads();
    for (int off = 64; off; off >>= 1) {
        if (tid < off) red[tid] += red[tid + off];
        __syncthreads();
    }
    if (tid == 0) {
        g_en[k] = red[0];
        g_counts[k] = 0;
        if (k == 0) g_nflag = 0;
    }
}

// ---------------------------------------------------------------------------
// conv_h: g_h -> bf16 hi/lo split
// ---------------------------------------------------------------------------
__global__ void conv_h_kernel()
{
    const size_t i = ((size_t)blockIdx.x * 256 + threadIdx.x) * 4;
    float4 v = *(const float4*)(g_h + i);
    __nv_bfloat16 hx = __float2bfloat16_rn(v.x), hy = __float2bfloat16_rn(v.y);
    __nv_bfloat16 hz = __float2bfloat16_rn(v.z), hw = __float2bfloat16_rn(v.w);
    __nv_bfloat16 lx = __float2bfloat16_rn(v.x - __bfloat162float(hx));
    __nv_bfloat16 ly = __float2bfloat16_rn(v.y - __bfloat162float(hy));
    __nv_bfloat16 lz = __float2bfloat16_rn(v.z - __bfloat162float(hz));
    __nv_bfloat16 lw = __float2bfloat16_rn(v.w - __bfloat162float(hw));
    *(__nv_bfloat162*)(g_hhi + i)     = __nv_bfloat162(hx, hy);
    *(__nv_bfloat162*)(g_hhi + i + 2) = __nv_bfloat162(hz, hw);
    *(__nv_bfloat162*)(g_hlo + i)     = __nv_bfloat162(lx, ly);
    *(__nv_bfloat162*)(g_hlo + i + 2) = __nv_bfloat162(lz, lw);
}

// ---------------------------------------------------------------------------
// GEMM2 via mma.sync bf16, virtual K = 1536:
//   phase 0: hhi . ehi   phase 1: hhi . elo   phase 2: hlo . ehi
// CTA = 128 rows; loops 16 N-tiles of 128 codes; fused in-register top-2
// argmin; rows with (min2-min1) <= MARGIN get exact fp32 fallback.
// ---------------------------------------------------------------------------
#define SPITCH 72   // bf16 elems per smem row (64 data + 8 pad): conflict-free frags

__global__ __launch_bounds__(256, 2)
void gemm2_mma_kernel()
{
    __shared__ __align__(16) char smem_raw[2 * 128 * SPITCH * 2];  // A + B tiles
    __nv_bfloat16* sA = (__nv_bfloat16*)smem_raw;
    __nv_bfloat16* sB = (__nv_bfloat16*)(smem_raw + 128 * SPITCH * 2);

    const int tid  = threadIdx.x;
    const int lane = tid & 31;
    const int w    = tid >> 5;
    const int wm   = w >> 2;        // 0..1  (M warp coord)
    const int wn   = w & 3;         // 0..3  (N warp coord)
    const int lq   = lane >> 2;     // lane/4
    const int lr   = lane & 3;      // lane%4
    const int m0   = blockIdx.x * 128;

    float v1[8], v2[8]; int i1[8];
#pragma unroll
    for (int s = 0; s < 8; s++) { v1[s] = 3.4e38f; v2[s] = 3.4e38f; i1[s] = 0; }

#define UPD(sl, cc, ss) do { float _s = (ss); \
    if (_s < v1[sl]) { v2[sl] = v1[sl]; v1[sl] = _s; i1[sl] = (cc); } \
    else if (_s < v2[sl]) v2[sl] = _s; } while (0)

    for (int nt = 0; nt < 16; nt++) {
        const int n0 = nt * 128;
        float acc[4][4][4];
#pragma unroll
        for (int a = 0; a < 4; a++)
#pragma unroll
            for (int b = 0; b < 4; b++)
#pragma unroll
                for (int c = 0; c < 4; c++) acc[a][b][c] = 0.0f;

        for (int vc = 0; vc < 24; vc++) {
            const int phase = vc >> 3;
            const int kk    = (vc & 7) * 64;
            const __nv_bfloat16* Ag = (phase < 2)  ? g_hhi : g_hlo;
            const __nv_bfloat16* Bg = (phase == 1) ? g_elo : g_ehi;
            // load 128x64 A and B chunks (16B per thread-iter)
#pragma unroll
            for (int i = 0; i < 4; i++) {
                int q = tid + i * 256;           // 0..1023
                int r = q >> 3, ch = q & 7;
                *(uint4*)(sA + r * SPITCH + ch * 8) =
                    *(const uint4*)(Ag + (size_t)(m0 + r) * D_DIM + kk + ch * 8);
                *(uint4*)(sB + r * SPITCH + ch * 8) =
                    *(const uint4*)(Bg + (size_t)(n0 + r) * D_DIM + kk + ch * 8);
            }
            __syncthreads();
#pragma unroll
            for (int ks = 0; ks < 4; ks++) {
                uint32_t bfr[4][2];
#pragma unroll
                for (int nn = 0; nn < 4; nn++) {
                    const __nv_bfloat16* bp = sB + (wn * 32 + nn * 8 + lq) * SPITCH + ks * 16 + lr * 2;
                    bfr[nn][0] = *(const uint32_t*)(bp);
                    bfr[nn][1] = *(const uint32_t*)(bp + 8);
                }
#pragma unroll
                for (int mt = 0; mt < 4; mt++) {
                    const __nv_bfloat16* ap = sA + (wm * 64 + mt * 16 + lq) * SPITCH + ks * 16 + lr * 2;
                    uint32_t afr[4];
                    afr[0] = *(const uint32_t*)(ap);
                    afr[1] = *(const uint32_t*)(ap + 8 * SPITCH);
                    afr[2] = *(const uint32_t*)(ap + 8);
                    afr[3] = *(const uint32_t*)(ap + 8 * SPITCH + 8);
#pragma unroll
                    for (int nn = 0; nn < 4; nn++)
                        mma16816(acc[mt][nn], afr, bfr[nn]);
                }
            }
            __syncthreads();
        }

        // fused score + top-2 update for this n-tile
#pragma unroll
        for (int mt = 0; mt < 4; mt++) {
#pragma unroll
            for (int nn = 0; nn < 4; nn++) {
                const int col = n0 + wn * 32 + nn * 8 + lr * 2;
                const float e0 = g_en[col], e1 = g_en[col + 1];
                const int s0 = mt * 2, s1 = mt * 2 + 1;
                UPD(s0, col,     e0 - 2.0f * acc[mt][nn][0]);
                UPD(s0, col + 1, e1 - 2.0f * acc[mt][nn][1]);
                UPD(s1, col,     e0 - 2.0f * acc[mt][nn][2]);
                UPD(s1, col + 1, e1 - 2.0f * acc[mt][nn][3]);
            }
        }
    }

    // reduce across the 4 lanes (lr) sharing each row
#pragma unroll
    for (int off = 1; off <= 2; off <<= 1) {
#pragma unroll
        for (int sl = 0; sl < 8; sl++) {
            float ov1 = __shfl_xor_sync(0xffffffffu, v1[sl], off);
            int   oi1 = __shfl_xor_sync(0xffffffffu, i1[sl], off);
            float ov2 = __shfl_xor_sync(0xffffffffu, v2[sl], off);
            if (ov1 < v1[sl] || (ov1 == v1[sl] && oi1 < i1[sl])) {
                v2[sl] = fminf(v1[sl], ov2); v1[sl] = ov1; i1[sl] = oi1;
            } else {
                v2[sl] = fminf(v2[sl], ov1);
            }
        }
    }

    // cross-warp (wn) reduction through smem overlay
    __syncthreads();
    float* rv1 = (float*)smem_raw;                 // 512 floats
    int*   ri1 = (int*)(smem_raw + 2048);          // 512 ints
    float* rv2 = (float*)(smem_raw + 4096);        // 512 floats
    if (lr == 0) {
#pragma unroll
        for (int sl = 0; sl < 8; sl++) {
            int row = wm * 64 + (sl >> 1) * 16 + (sl & 1) * 8 + lq;
            rv1[row * 4 + wn] = v1[sl];
            ri1[row * 4 + wn] = i1[sl];
            rv2[row * 4 + wn] = v2[sl];
        }
    }
    __syncthreads();
    if (tid < 128) {
        float bv1 = rv1[tid * 4]; int bi1 = ri1[tid * 4]; float bv2 = rv2[tid * 4];
#pragma unroll
        for (int j = 1; j < 4; j++) {
            float ov1 = rv1[tid * 4 + j]; int oi1 = ri1[tid * 4 + j]; float ov2 = rv2[tid * 4 + j];
            if (ov1 < bv1 || (ov1 == bv1 && oi1 < bi1)) {
                bv2 = fminf(bv1, ov2); bv1 = ov1; bi1 = oi1;
            } else {
                bv2 = fminf(bv2, ov1);
            }
        }
        const int row = m0 + tid;
        g_idx[row] = bi1;
        if (bv2 - bv1 <= MARGIN) {
            int slot = atomicAdd(&g_nflag, 1);
            g_flagged[slot] = row;
        }
    }
}

// ---------------------------------------------------------------------------
// Fallback: exact fp32 argmin for flagged rows (emb stays L2-resident)
// ---------------------------------------------------------------------------
__global__ __launch_bounds__(256)
void fallback_kernel(const float* __restrict__ emb)
{
    __shared__ float hrow[D_DIM];
    __shared__ float rv[256];
    __shared__ int   ri[256];
    const int tid = threadIdx.x;
    const int cnt = g_nflag;

    for (int f = blockIdx.x; f < cnt; f += gridDim.x) {
        const int row = g_flagged[f];
        if (tid < 128) *(float4*)(hrow + tid * 4) = *(const float4*)(g_h + (size_t)row * D_DIM + tid * 4);
        __syncthreads();

        float bestv = 3.4e38f;
        int   besti = 0;
        for (int k = tid; k < K_CODES; k += 256) {
            const float4* ep = (const float4*)(emb + (size_t)k * D_DIM);
            float acc = 0.0f;
#pragma unroll 4
            for (int d4 = 0; d4 < D_DIM / 4; d4++) {
                float4 e = ep[d4];
                float4 h = *(const float4*)(hrow + d4 * 4);
                acc += e.x * h.x + e.y * h.y + e.z * h.z + e.w * h.w;
            }
            float s = g_en[k] - 2.0f * acc;
            if (s < bestv) { bestv = s; besti = k; }
        }
        rv[tid] = bestv; ri[tid] = besti;
        __syncthreads();
        for (int off = 128; off; off >>= 1) {
            if (tid < off) {
                float ov = rv[tid + off]; int oi = ri[tid + off];
                if (ov < rv[tid] || (ov == rv[tid] && oi < ri[tid])) { rv[tid] = ov; ri[tid] = oi; }
            }
            __syncthreads();
        }
        if (tid == 0) g_idx[row] = ri[0];
        __syncthreads();
    }
}

// ---------------------------------------------------------------------------
// Epilogue per row: q_out, encodings, loss partial, counts
// ---------------------------------------------------------------------------
__global__ void epilogue_kernel(const float* __restrict__ emb, float* __restrict__ out)
{
    __shared__ float red[128];
    const int n   = blockIdx.x;
    const int tid = threadIdx.x;
    const int idx = g_idx[n];

    float4 hv = *(const float4*)(g_h + (size_t)n * D_DIM + tid * 4);
    float4 qv = *(const float4*)(emb + (size_t)idx * D_DIM + tid * 4);
    float d0 = qv.x - hv.x, d1 = qv.y - hv.y, d2 = qv.z - hv.z, d3 = qv.w - hv.w;

    float* qo = out + OFF_QOUT + (size_t)n * D_DIM + tid * 4;
    qo[0] = hv.x + d0; qo[1] = hv.y + d1; qo[2] = hv.z + d2; qo[3] = hv.w + d3;

    red[tid] = d0 * d0 + d1 * d1 + d2 * d2 + d3 * d3;

    float2* er2 = (float2*)(out + OFF_ENC + (size_t)n * K_CODES);
    const int unit = idx >> 1, comp = idx & 1;
#pragma unroll
    for (int i = 0; i < 8; i++) {
        int u = tid + i * 128;
        float2 v = make_float2(0.0f, 0.0f);
        if (u == unit) { if (comp == 0) v.x = 1.0f; else v.y = 1.0f; }
        er2[u] = v;
    }

    __syncthreads();
    for (int off = 64; off; off >>= 1) {
        if (tid < off) red[tid] += red[tid + off];
        __syncthreads();
    }
    if (tid == 0) {
        g_partial[n] = red[0];
        atomicAdd(&g_counts[idx], 1);
    }
}

// ---------------------------------------------------------------------------
__global__ void final_kernel(float* __restrict__ out)
{
    __shared__ float red[1024];
    const int tid = threadIdx.x;

    float s = 0.0f;
    for (int i = 0; i < N_ROWS / 1024; i++) s += g_partial[tid + i * 1024];
    red[tid] = s;
    __syncthreads();
    for (int off = 512; off; off >>= 1) {
        if (tid < off) red[tid] += red[tid + off];
        __syncthreads();
    }
    if (tid == 0) out[0] = 0.25f * red[0] / (float)((size_t)N_ROWS * D_DIM);
    __syncthreads();

    float p = 0.0f;
    for (int i = 0; i < K_CODES / 1024; i++) {
        float c  = (float)g_counts[tid + i * 1024];
        float pr = c * (1.0f / (float)N_ROWS);
        p += pr * logf(pr + 1e-10f);
    }
    red[tid] = p;
    __syncthreads();
    for (int off = 512; off; off >>= 1) {
        if (tid < off) red[tid] += red[tid + off];
        __syncthreads();
    }
    if (tid == 0) out[OFF_PERP] = expf(-red[0]);
}

// ---------------------------------------------------------------------------
extern "C" void kernel_launch(void* const* d_in, const int* in_sizes, int n_in,
                              void* d_out, int out_size)
{
    const float *x0 = nullptr, *x1 = nullptr, *W = nullptr, *b = nullptr, *emb = nullptr;
    for (int i = 0; i < n_in; i++) {
        const float* p = (const float*)d_in[i];
        const long long s = in_sizes[i];
        if (s == (long long)N_ROWS * HALFW)       { if (!x0) x0 = p; else x1 = p; }
        else if (s == (long long)D_DIM * D_DIM)   W = p;
        else if (s == (long long)D_DIM)           b = p;
        else if (s == (long long)K_CODES * D_DIM) emb = p;
    }
    float* out = (float*)d_out;

    gemm1_kernel<<<dim3(D_DIM / 128, N_ROWS / 128), 256>>>(x0, x1, W, b);
    prep_emb_kernel<<<K_CODES, 128>>>(emb);
    conv_h_kernel<<<(N_ROWS * D_DIM) / 1024, 256>>>();
    gemm2_mma_kernel<<<N_ROWS / 128, 256>>>();
    fallback_kernel<<<256, 256>>>(emb);
    epilogue_kernel<<<N_ROWS, 128>>>(emb, out);
    final_kernel<<<1, 1024>>>(out);
}

// round 4
// speedup vs baseline: 1.6206x; 1.0543x over previous
#include <cuda_runtime.h>
#include <cuda_bf16.h>
#include <math.h>
#include <stdint.h>

// Problem constants
#define N_ROWS  32768
#define D_DIM   512
#define K_CODES 2048
#define HALFW   256

// Output layout: [loss(1) | q_out(2*32768*256) | perplexity(1) | encodings(32768*2048)]
#define OFF_QOUT 1
#define OFF_PERP (1 + N_ROWS * D_DIM)
#define OFF_ENC  (2 + N_ROWS * D_DIM)

#define MARGIN 0.05f

// Scratch (device globals: allocation-free per harness rules)
__device__ float         g_h[(size_t)N_ROWS * D_DIM];
__device__ __nv_bfloat16 g_hhi[(size_t)N_ROWS * D_DIM];
__device__ __nv_bfloat16 g_hlo[(size_t)N_ROWS * D_DIM];
__device__ __nv_bfloat16 g_ehi[(size_t)K_CODES * D_DIM];
__device__ __nv_bfloat16 g_elo[(size_t)K_CODES * D_DIM];
__device__ float g_en[K_CODES];
__device__ int   g_idx[N_ROWS];
__device__ float g_partial[N_ROWS];
__device__ int   g_counts[K_CODES];
__device__ int   g_nflag;
__device__ int   g_flagged[N_ROWS];

// ---------------------------------------------------------------------------
// mma.sync m16n8k16 bf16 (HMMA, base sm_100)
// ---------------------------------------------------------------------------
__device__ __forceinline__ void mma16816(float* c, const uint32_t* a, const uint32_t* b) {
    asm volatile(
        "mma.sync.aligned.m16n8k16.row.col.f32.bf16.bf16.f32 "
        "{%0,%1,%2,%3}, {%4,%5,%6,%7}, {%8,%9}, {%0,%1,%2,%3};"
        : "+f"(c[0]), "+f"(c[1]), "+f"(c[2]), "+f"(c[3])
        : "r"(a[0]), "r"(a[1]), "r"(a[2]), "r"(a[3]), "r"(b[0]), "r"(b[1]));
}

__device__ __forceinline__ void cp16(void* dst_smem, const void* src) {
    uint32_t d = (uint32_t)__cvta_generic_to_shared(dst_smem);
    asm volatile("cp.async.cg.shared.global [%0], [%1], 16;" :: "r"(d), "l"(src));
}
#define CP_COMMIT() asm volatile("cp.async.commit_group;" ::: "memory")
#define CP_WAIT(N)  asm volatile("cp.async.wait_group %0;" :: "n"(N) : "memory")

// ---------------------------------------------------------------------------
// GEMM1: g_h = concat(x0,x1) @ W^T + b   (fp32 exact) + fused bf16 hi/lo split
// ---------------------------------------------------------------------------
__global__ __launch_bounds__(256, 2)
void gemm1_kernel(const float* __restrict__ x0, const float* __restrict__ x1,
                  const float* __restrict__ W, const float* __restrict__ bias)
{
    __shared__ float As[16][128];
    __shared__ float Bs[16][128];
    const int m0  = blockIdx.y * 128;
    const int n0  = blockIdx.x * 128;
    const int tid = threadIdx.x;
    const int tx  = tid & 15, ty = tid >> 4;

    float acc[8][8];
#pragma unroll
    for (int i = 0; i < 8; i++)
#pragma unroll
        for (int j = 0; j < 8; j++) acc[i][j] = 0.0f;

    for (int kt = 0; kt < D_DIM; kt += 16) {
        const float* Asrc = (kt < HALFW) ? x0 : x1;
        const int    kc   = (kt < HALFW) ? kt : (kt - HALFW);
#pragma unroll
        for (int r = 0; r < 2; r++) {
            int q = tid + r * 256, row = q >> 2, c4 = (q & 3) << 2;
            float4 v = *(const float4*)(Asrc + (size_t)(m0 + row) * HALFW + kc + c4);
            As[c4 + 0][row] = v.x; As[c4 + 1][row] = v.y;
            As[c4 + 2][row] = v.z; As[c4 + 3][row] = v.w;
        }
#pragma unroll
        for (int r = 0; r < 2; r++) {
            int q = tid + r * 256, row = q >> 2, c4 = (q & 3) << 2;
            float4 v = *(const float4*)(W + (size_t)(n0 + row) * D_DIM + kt + c4);
            Bs[c4 + 0][row] = v.x; Bs[c4 + 1][row] = v.y;
            Bs[c4 + 2][row] = v.z; Bs[c4 + 3][row] = v.w;
        }
        __syncthreads();
#pragma unroll
        for (int kk = 0; kk < 16; kk++) {
            float a[8], b[8];
#pragma unroll
            for (int i = 0; i < 8; i++) a[i] = As[kk][ty * 8 + i];
#pragma unroll
            for (int j = 0; j < 8; j++) b[j] = Bs[kk][tx * 8 + j];
#pragma unroll
            for (int i = 0; i < 8; i++)
#pragma unroll
                for (int j = 0; j < 8; j++)
                    acc[i][j] += a[i] * b[j];
        }
        __syncthreads();
    }
#pragma unroll
    for (int i = 0; i < 8; i++) {
        int row = m0 + ty * 8 + i;
#pragma unroll
        for (int j = 0; j < 8; j += 4) {
            int col = n0 + tx * 8 + j;
            float4 v;
            v.x = acc[i][j + 0] + bias[col + 0];
            v.y = acc[i][j + 1] + bias[col + 1];
            v.z = acc[i][j + 2] + bias[col + 2];
            v.w = acc[i][j + 3] + bias[col + 3];
            const size_t o = (size_t)row * D_DIM + col;
            *(float4*)(g_h + o) = v;
            // fused bf16 hi/lo split
            __nv_bfloat16 hx = __float2bfloat16_rn(v.x), hy = __float2bfloat16_rn(v.y);
            __nv_bfloat16 hz = __float2bfloat16_rn(v.z), hw = __float2bfloat16_rn(v.w);
            __nv_bfloat16 lx = __float2bfloat16_rn(v.x - __bfloat162float(hx));
            __nv_bfloat16 ly = __float2bfloat16_rn(v.y - __bfloat162float(hy));
            __nv_bfloat16 lz = __float2bfloat16_rn(v.z - __bfloat162float(hz));
            __nv_bfloat16 lw = __float2bfloat16_rn(v.w - __bfloat162float(hw));
            *(__nv_bfloat162*)(g_hhi + o)     = __nv_bfloat162(hx, hy);
            *(__nv_bfloat162*)(g_hhi + o + 2) = __nv_bfloat162(hz, hw);
            *(__nv_bfloat162*)(g_hlo + o)     = __nv_bfloat162(lx, ly);
            *(__nv_bfloat162*)(g_hlo + o + 2) = __nv_bfloat162(lz, lw);
        }
    }
}

// ---------------------------------------------------------------------------
// prep_emb: ||e_k||^2 (fp32 exact), e -> bf16 hi/lo split, zero counts/nflag
// ---------------------------------------------------------------------------
__global__ void prep_emb_kernel(const float* __restrict__ emb)
{
    __shared__ float red[128];
    const int k   = blockIdx.x;
    const int tid = threadIdx.x;
    const size_t base = (size_t)k * D_DIM + tid * 4;
    float4 v = *(const float4*)(emb + base);
    red[tid] = v.x * v.x + v.y * v.y + v.z * v.z + v.w * v.w;

    __nv_bfloat16 hx = __float2bfloat16_rn(v.x), hy = __float2bfloat16_rn(v.y);
    __nv_bfloat16 hz = __float2bfloat16_rn(v.z), hw = __float2bfloat16_rn(v.w);
    __nv_bfloat16 lx = __float2bfloat16_rn(v.x - __bfloat162float(hx));
    __nv_bfloat16 ly = __float2bfloat16_rn(v.y - __bfloat162float(hy));
    __nv_bfloat16 lz = __float2bfloat16_rn(v.z - __bfloat162float(hz));
    __nv_bfloat16 lw = __float2bfloat16_rn(v.w - __bfloat162float(hw));
    *(__nv_bfloat162*)(g_ehi + base)     = __nv_bfloat162(hx, hy);
    *(__nv_bfloat162*)(g_ehi + base + 2) = __nv_bfloat162(hz, hw);
    *(__nv_bfloat162*)(g_elo + base)     = __nv_bfloat162(lx, ly);
    *(__nv_bfloat162*)(g_elo + base + 2) = __nv_bfloat162(lz, lw);

    __syncthreads();
    for (int off = 64; off; off >>= 1) {
        if (tid < off) red[tid] += red[tid + off];
        __syncthreads();
    }
    if (tid == 0) {
        g_en[k] = red[0];
        g_counts[k] = 0;
        if (k == 0) g_nflag = 0;
    }
}

// ---------------------------------------------------------------------------
// GEMM2 via mma.sync bf16, virtual K = 1536 (3 phases), 2-stage cp.async
// pipeline. CTA = 128 rows; 16 N-tiles of 128 codes; fused in-register top-2
// argmin; rows with (min2-min1) <= MARGIN get exact fp32 fallback.
// ---------------------------------------------------------------------------
#define SPITCH 72                       // bf16/row (64 data + 8 pad), 144B = 9*16B
#define STAGE_BYTES (128 * SPITCH * 2)  // 18432 per tile
#define NSTEP 384                       // 16 nt * 24 vc

__global__ __launch_bounds__(256, 2)
void gemm2_mma_kernel()
{
    extern __shared__ __align__(16) char dsm[];
    // stage s: A at dsm + s*2*STAGE_BYTES, B at +STAGE_BYTES
    const int tid  = threadIdx.x;
    const int lane = tid & 31;
    const int w    = tid >> 5;
    const int wm   = w >> 2;        // 0..1
    const int wn   = w & 3;         // 0..3
    const int lq   = lane >> 2;
    const int lr   = lane & 3;
    const int m0   = blockIdx.x * 128;

    // per-thread load coords (4 chunks of 16B for A, same for B)
    const int lrow0 = tid >> 3;         // rows tid/8 + {0,32,64,96}
    const int lch   = tid & 7;          // 16B chunk in row

    float v1[8], v2[8]; int i1[8];
#pragma unroll
    for (int s = 0; s < 8; s++) { v1[s] = 3.4e38f; v2[s] = 3.4e38f; i1[s] = 0; }

#define UPD(sl, cc, ss) do { float _s = (ss); \
    if (_s < v1[sl]) { v2[sl] = v1[sl]; v1[sl] = _s; i1[sl] = (cc); } \
    else if (_s < v2[sl]) v2[sl] = _s; } while (0)

    // ---- async tile loader for flattened step = nt*24 + vc
    auto load_step = [&](int step, int stage) {
        const int nt    = step / 24;
        const int vc    = step - nt * 24;
        const int phase = vc >> 3;
        const int kk    = (vc & 7) * 64;
        const int n0    = nt * 128;
        const __nv_bfloat16* Ag = (phase < 2)  ? g_hhi : g_hlo;
        const __nv_bfloat16* Bg = (phase == 1) ? g_elo : g_ehi;
        char* sAb = dsm + stage * 2 * STAGE_BYTES;
        char* sBb = sAb + STAGE_BYTES;
#pragma unroll
        for (int i = 0; i < 4; i++) {
            int r = lrow0 + i * 32;
            size_t goA = (size_t)(m0 + r) * D_DIM + kk + lch * 8;
            size_t goB = (size_t)(n0 + r) * D_DIM + kk + lch * 8;
            cp16(sAb + (r * SPITCH + lch * 8) * 2, Ag + goA);
            cp16(sBb + (r * SPITCH + lch * 8) * 2, Bg + goB);
        }
    };

    load_step(0, 0);
    CP_COMMIT();

    float acc[4][4][4];
    for (int nt = 0; nt < 16; nt++) {
        const int n0 = nt * 128;
#pragma unroll
        for (int a = 0; a < 4; a++)
#pragma unroll
            for (int b = 0; b < 4; b++)
#pragma unroll
                for (int c = 0; c < 4; c++) acc[a][b][c] = 0.0f;

        for (int vc = 0; vc < 24; vc++) {
            const int cur = nt * 24 + vc;
            if (cur + 1 < NSTEP) {
                load_step(cur + 1, (cur + 1) & 1);
                CP_COMMIT();
                CP_WAIT(1);
            } else {
                CP_WAIT(0);
            }
            __syncthreads();

            const __nv_bfloat16* sA =
                (const __nv_bfloat16*)(dsm + (cur & 1) * 2 * STAGE_BYTES);
            const __nv_bfloat16* sB =
                (const __nv_bfloat16*)((const char*)sA + STAGE_BYTES);
#pragma unroll
            for (int ks = 0; ks < 4; ks++) {
                uint32_t bfr[4][2];
#pragma unroll
                for (int nn = 0; nn < 4; nn++) {
                    const __nv_bfloat16* bp = sB + (wn * 32 + nn * 8 + lq) * SPITCH + ks * 16 + lr * 2;
                    bfr[nn][0] = *(const uint32_t*)(bp);
                    bfr[nn][1] = *(const uint32_t*)(bp + 8);
                }
#pragma unroll
                for (int mt = 0; mt < 4; mt++) {
                    const __nv_bfloat16* ap = sA + (wm * 64 + mt * 16 + lq) * SPITCH + ks * 16 + lr * 2;
                    uint32_t afr[4];
                    afr[0] = *(const uint32_t*)(ap);
                    afr[1] = *(const uint32_t*)(ap + 8 * SPITCH);
                    afr[2] = *(const uint32_t*)(ap + 8);
                    afr[3] = *(const uint32_t*)(ap + 8 * SPITCH + 8);
#pragma unroll
                    for (int nn = 0; nn < 4; nn++)
                        mma16816(acc[mt][nn], afr, bfr[nn]);
                }
            }
            __syncthreads();
        }

        // fused score + top-2 update for this n-tile
#pragma unroll
        for (int mt = 0; mt < 4; mt++) {
#pragma unroll
            for (int nn = 0; nn < 4; nn++) {
                const int col = n0 + wn * 32 + nn * 8 + lr * 2;
                const float e0 = g_en[col], e1 = g_en[col + 1];
                const int s0 = mt * 2, s1 = mt * 2 + 1;
                UPD(s0, col,     e0 - 2.0f * acc[mt][nn][0]);
                UPD(s0, col + 1, e1 - 2.0f * acc[mt][nn][1]);
                UPD(s1, col,     e0 - 2.0f * acc[mt][nn][2]);
                UPD(s1, col + 1, e1 - 2.0f * acc[mt][nn][3]);
            }
        }
    }

    // reduce across the 4 lanes (lr) sharing each row
#pragma unroll
    for (int off = 1; off <= 2; off <<= 1) {
#pragma unroll
        for (int sl = 0; sl < 8; sl++) {
            float ov1 = __shfl_xor_sync(0xffffffffu, v1[sl], off);
            int   oi1 = __shfl_xor_sync(0xffffffffu, i1[sl], off);
            float ov2 = __shfl_xor_sync(0xffffffffu, v2[sl], off);
            if (ov1 < v1[sl] || (ov1 == v1[sl] && oi1 < i1[sl])) {
                v2[sl] = fminf(v1[sl], ov2); v1[sl] = ov1; i1[sl] = oi1;
            } else {
                v2[sl] = fminf(v2[sl], ov1);
            }
        }
    }

    // cross-warp (wn) reduction through smem overlay
    __syncthreads();
    float* rv1 = (float*)dsm;
    int*   ri1 = (int*)(dsm + 2048);
    float* rv2 = (float*)(dsm + 4096);
    if (lr == 0) {
#pragma unroll
        for (int sl = 0; sl < 8; sl++) {
            int row = wm * 64 + (sl >> 1) * 16 + (sl & 1) * 8 + lq;
            rv1[row * 4 + wn] = v1[sl];
            ri1[row * 4 + wn] = i1[sl];
            rv2[row * 4 + wn] = v2[sl];
        }
    }
    __syncthreads();
    if (tid < 128) {
        float bv1 = rv1[tid * 4]; int bi1 = ri1[tid * 4]; float bv2 = rv2[tid * 4];
#pragma unroll
        for (int j = 1; j < 4; j++) {
            float ov1 = rv1[tid * 4 + j]; int oi1 = ri1[tid * 4 + j]; float ov2 = rv2[tid * 4 + j];
            if (ov1 < bv1 || (ov1 == bv1 && oi1 < bi1)) {
                bv2 = fminf(bv1, ov2); bv1 = ov1; bi1 = oi1;
            } else {
                bv2 = fminf(bv2, ov1);
            }
        }
        const int row = m0 + tid;
        g_idx[row] = bi1;
        if (bv2 - bv1 <= MARGIN) {
            int slot = atomicAdd(&g_nflag, 1);
            g_flagged[slot] = row;
        }
    }
}

// ---------------------------------------------------------------------------
// Fallback: exact fp32 argmin for flagged rows (emb stays L2-resident)
// ---------------------------------------------------------------------------
__global__ __launch_bounds__(256)
void fallback_kernel(const float* __restrict__ emb)
{
    __shared__ float hrow[D_DIM];
    __shared__ float rv[256];
    __shared__ int   ri[256];
    const int tid = threadIdx.x;
    const int cnt = g_nflag;

    for (int f = blockIdx.x; f < cnt; f += gridDim.x) {
        const int row = g_flagged[f];
        if (tid < 128) *(float4*)(hrow + tid * 4) = *(const float4*)(g_h + (size_t)row * D_DIM + tid * 4);
        __syncthreads();

        float bestv = 3.4e38f;
        int   besti = 0;
        for (int k = tid; k < K_CODES; k += 256) {
            const float4* ep = (const float4*)(emb + (size_t)k * D_DIM);
            float acc = 0.0f;
#pragma unroll 4
            for (int d4 = 0; d4 < D_DIM / 4; d4++) {
                float4 e = ep[d4];
                float4 h = *(const float4*)(hrow + d4 * 4);
                acc += e.x * h.x + e.y * h.y + e.z * h.z + e.w * h.w;
            }
            float s = g_en[k] - 2.0f * acc;
            if (s < bestv) { bestv = s; besti = k; }
        }
        rv[tid] = bestv; ri[tid] = besti;
        __syncthreads();
        for (int off = 128; off; off >>= 1) {
            if (tid < off) {
                float ov = rv[tid + off]; int oi = ri[tid + off];
                if (ov < rv[tid] || (ov == rv[tid] && oi < ri[tid])) { rv[tid] = ov; ri[tid] = oi; }
            }
            __syncthreads();
        }
        if (tid == 0) g_idx[row] = ri[0];
        __syncthreads();
    }
}

// ---------------------------------------------------------------------------
// Epilogue per row: q_out, encodings, loss partial, counts
// ---------------------------------------------------------------------------
__global__ void epilogue_kernel(const float* __restrict__ emb, float* __restrict__ out)
{
    __shared__ float red[128];
    const int n   = blockIdx.x;
    const int tid = threadIdx.x;
    const int idx = g_idx[n];

    float4 hv = *(const float4*)(g_h + (size_t)n * D_DIM + tid * 4);
    float4 qv = *(const float4*)(emb + (size_t)idx * D_DIM + tid * 4);
    float d0 = qv.x - hv.x, d1 = qv.y - hv.y, d2 = qv.z - hv.z, d3 = qv.w - hv.w;

    float* qo = out + OFF_QOUT + (size_t)n * D_DIM + tid * 4;
    qo[0] = hv.x + d0; qo[1] = hv.y + d1; qo[2] = hv.z + d2; qo[3] = hv.w + d3;

    red[tid] = d0 * d0 + d1 * d1 + d2 * d2 + d3 * d3;

    float2* er2 = (float2*)(out + OFF_ENC + (size_t)n * K_CODES);
    const int unit = idx >> 1, comp = idx & 1;
#pragma unroll
    for (int i = 0; i < 8; i++) {
        int u = tid + i * 128;
        float2 v = make_float2(0.0f, 0.0f);
        if (u == unit) { if (comp == 0) v.x = 1.0f; else v.y = 1.0f; }
        er2[u] = v;
    }

    __syncthreads();
    for (int off = 64; off; off >>= 1) {
        if (tid < off) red[tid] += red[tid + off];
        __syncthreads();
    }
    if (tid == 0) {
        g_partial[n] = red[0];
        atomicAdd(&g_counts[idx], 1);
    }
}

// ---------------------------------------------------------------------------
__global__ void final_kernel(float* __restrict__ out)
{
    __shared__ float red[1024];
    const int tid = threadIdx.x;

    float s = 0.0f;
    for (int i = 0; i < N_ROWS / 1024; i++) s += g_partial[tid + i * 1024];
    red[tid] = s;
    __syncthreads();
    for (int off = 512; off; off >>= 1) {
        if (tid < off) red[tid] += red[tid + off];
        __syncthreads();
    }
    if (tid == 0) out[0] = 0.25f * red[0] / (float)((size_t)N_ROWS * D_DIM);
    __syncthreads();

    float p = 0.0f;
    for (int i = 0; i < K_CODES / 1024; i++) {
        float c  = (float)g_counts[tid + i * 1024];
        float pr = c * (1.0f / (float)N_ROWS);
        p += pr * logf(pr + 1e-10f);
    }
    red[tid] = p;
    __syncthreads();
    for (int off = 512; off; off >>= 1) {
        if (tid < off) red[tid] += red[tid + off];
        __syncthreads();
    }
    if (tid == 0) out[OFF_PERP] = expf(-red[0]);
}

// ---------------------------------------------------------------------------
extern "C" void kernel_launch(void* const* d_in, const int* in_sizes, int n_in,
                              void* d_out, int out_size)
{
    const float *x0 = nullptr, *x1 = nullptr, *W = nullptr, *b = nullptr, *emb = nullptr;
    for (int i = 0; i < n_in; i++) {
        const float* p = (const float*)d_in[i];
        const long long s = in_sizes[i];
        if (s == (long long)N_ROWS * HALFW)       { if (!x0) x0 = p; else x1 = p; }
        else if (s == (long long)D_DIM * D_DIM)   W = p;
        else if (s == (long long)D_DIM)           b = p;
        else if (s == (long long)K_CODES * D_DIM) emb = p;
    }
    float* out = (float*)d_out;

    static int smem_set = 0;
    if (!smem_set) {
        cudaFuncSetAttribute(gemm2_mma_kernel,
                             cudaFuncAttributeMaxDynamicSharedMemorySize,
                             4 * STAGE_BYTES);
        smem_set = 1;
    }

    gemm1_kernel<<<dim3(D_DIM / 128, N_ROWS / 128), 256>>>(x0, x1, W, b);
    prep_emb_kernel<<<K_CODES, 128>>>(emb);
    gemm2_mma_kernel<<<N_ROWS / 128, 256, 4 * STAGE_BYTES>>>();
    fallback_kernel<<<256, 256>>>(emb);
    epilogue_kernel<<<N_ROWS, 128>>>(emb, out);
    final_kernel<<<1, 1024>>>(out);
}

// round 5
// speedup vs baseline: 1.9838x; 1.2241x over previous
#include <cuda_runtime.h>
#include <cuda_bf16.h>
#include <math.h>
#include <stdint.h>

// Problem constants
#define N_ROWS  32768
#define D_DIM   512
#define K_CODES 2048
#define HALFW   256

// Output layout: [loss(1) | q_out(2*32768*256) | perplexity(1) | encodings(32768*2048)]
#define OFF_QOUT 1
#define OFF_PERP (1 + N_ROWS * D_DIM)
#define OFF_ENC  (2 + N_ROWS * D_DIM)

#define MARGIN 0.02f

// Scratch (device globals: allocation-free per harness rules)
__device__ float         g_h[(size_t)N_ROWS * D_DIM];
__device__ __nv_bfloat16 g_hhi[(size_t)N_ROWS * D_DIM];
__device__ __nv_bfloat16 g_hlo[(size_t)N_ROWS * D_DIM];
__device__ __nv_bfloat16 g_ehi[(size_t)K_CODES * D_DIM];
__device__ __nv_bfloat16 g_elo[(size_t)K_CODES * D_DIM];
__device__ float g_en[K_CODES];
__device__ int   g_idx[N_ROWS];
__device__ float g_partial[N_ROWS];
__device__ int   g_counts[K_CODES];
__device__ int   g_nflag;
__device__ int   g_flagged[N_ROWS];
__device__ unsigned long long g_best[N_ROWS];

// ---------------------------------------------------------------------------
// PTX helpers
// ---------------------------------------------------------------------------
__device__ __forceinline__ void mma16816(float* c, const uint32_t* a, const uint32_t* b) {
    asm volatile(
        "mma.sync.aligned.m16n8k16.row.col.f32.bf16.bf16.f32 "
        "{%0,%1,%2,%3}, {%4,%5,%6,%7}, {%8,%9}, {%0,%1,%2,%3};"
        : "+f"(c[0]), "+f"(c[1]), "+f"(c[2]), "+f"(c[3])
        : "r"(a[0]), "r"(a[1]), "r"(a[2]), "r"(a[3]), "r"(b[0]), "r"(b[1]));
}
__device__ __forceinline__ void ldsm_x4(uint32_t* r, uint32_t addr) {
    asm volatile("ldmatrix.sync.aligned.m8n8.x4.shared.b16 {%0,%1,%2,%3}, [%4];"
                 : "=r"(r[0]), "=r"(r[1]), "=r"(r[2]), "=r"(r[3]) : "r"(addr));
}
__device__ __forceinline__ void cp16(uint32_t dst_smem, const void* src) {
    asm volatile("cp.async.cg.shared.global [%0], [%1], 16;" :: "r"(dst_smem), "l"(src));
}
#define CP_COMMIT() asm volatile("cp.async.commit_group;" ::: "memory")
#define CP_WAIT(N)  asm volatile("cp.async.wait_group %0;" :: "n"(N) : "memory")

__device__ __forceinline__ uint32_t fmap(float f) {  // order-preserving float->uint
    uint32_t u = __float_as_uint(f);
    return (u & 0x80000000u) ? ~u : (u | 0x80000000u);
}

// ---------------------------------------------------------------------------
// GEMM1: g_h = concat(x0,x1) @ W^T + b   (fp32 exact) + fused bf16 hi/lo split
// ---------------------------------------------------------------------------
__global__ __launch_bounds__(256, 2)
void gemm1_kernel(const float* __restrict__ x0, const float* __restrict__ x1,
                  const float* __restrict__ W, const float* __restrict__ bias)
{
    __shared__ float As[16][128];
    __shared__ float Bs[16][128];
    const int m0  = blockIdx.y * 128;
    const int n0  = blockIdx.x * 128;
    const int tid = threadIdx.x;
    const int tx  = tid & 15, ty = tid >> 4;

    float acc[8][8];
#pragma unroll
    for (int i = 0; i < 8; i++)
#pragma unroll
        for (int j = 0; j < 8; j++) acc[i][j] = 0.0f;

    for (int kt = 0; kt < D_DIM; kt += 16) {
        const float* Asrc = (kt < HALFW) ? x0 : x1;
        const int    kc   = (kt < HALFW) ? kt : (kt - HALFW);
#pragma unroll
        for (int r = 0; r < 2; r++) {
            int q = tid + r * 256, row = q >> 2, c4 = (q & 3) << 2;
            float4 v = *(const float4*)(Asrc + (size_t)(m0 + row) * HALFW + kc + c4);
            As[c4 + 0][row] = v.x; As[c4 + 1][row] = v.y;
            As[c4 + 2][row] = v.z; As[c4 + 3][row] = v.w;
        }
#pragma unroll
        for (int r = 0; r < 2; r++) {
            int q = tid + r * 256, row = q >> 2, c4 = (q & 3) << 2;
            float4 v = *(const float4*)(W + (size_t)(n0 + row) * D_DIM + kt + c4);
            Bs[c4 + 0][row] = v.x; Bs[c4 + 1][row] = v.y;
            Bs[c4 + 2][row] = v.z; Bs[c4 + 3][row] = v.w;
        }
        __syncthreads();
#pragma unroll
        for (int kk = 0; kk < 16; kk++) {
            float a[8], b[8];
#pragma unroll
            for (int i = 0; i < 8; i++) a[i] = As[kk][ty * 8 + i];
#pragma unroll
            for (int j = 0; j < 8; j++) b[j] = Bs[kk][tx * 8 + j];
#pragma unroll
            for (int i = 0; i < 8; i++)
#pragma unroll
                for (int j = 0; j < 8; j++)
                    acc[i][j] += a[i] * b[j];
        }
        __syncthreads();
    }
#pragma unroll
    for (int i = 0; i < 8; i++) {
        int row = m0 + ty * 8 + i;
#pragma unroll
        for (int j = 0; j < 8; j += 4) {
            int col = n0 + tx * 8 + j;
            float4 v;
            v.x = acc[i][j + 0] + bias[col + 0];
            v.y = acc[i][j + 1] + bias[col + 1];
            v.z = acc[i][j + 2] + bias[col + 2];
            v.w = acc[i][j + 3] + bias[col + 3];
            const size_t o = (size_t)row * D_DIM + col;
            *(float4*)(g_h + o) = v;
            __nv_bfloat16 hx = __float2bfloat16_rn(v.x), hy = __float2bfloat16_rn(v.y);
            __nv_bfloat16 hz = __float2bfloat16_rn(v.z), hw = __float2bfloat16_rn(v.w);
            __nv_bfloat16 lx = __float2bfloat16_rn(v.x - __bfloat162float(hx));
            __nv_bfloat16 ly = __float2bfloat16_rn(v.y - __bfloat162float(hy));
            __nv_bfloat16 lz = __float2bfloat16_rn(v.z - __bfloat162float(hz));
            __nv_bfloat16 lw = __float2bfloat16_rn(v.w - __bfloat162float(hw));
            *(__nv_bfloat162*)(g_hhi + o)     = __nv_bfloat162(hx, hy);
            *(__nv_bfloat162*)(g_hhi + o + 2) = __nv_bfloat162(hz, hw);
            *(__nv_bfloat162*)(g_hlo + o)     = __nv_bfloat162(lx, ly);
            *(__nv_bfloat162*)(g_hlo + o + 2) = __nv_bfloat162(lz, lw);
        }
    }
}

// ---------------------------------------------------------------------------
// prep_emb: ||e_k||^2 (fp32 exact), e -> bf16 hi/lo split, zero counts/nflag
// ---------------------------------------------------------------------------
__global__ void prep_emb_kernel(const float* __restrict__ emb)
{
    __shared__ float red[128];
    const int k   = blockIdx.x;
    const int tid = threadIdx.x;
    const size_t base = (size_t)k * D_DIM + tid * 4;
    float4 v = *(const float4*)(emb + base);
    red[tid] = v.x * v.x + v.y * v.y + v.z * v.z + v.w * v.w;

    __nv_bfloat16 hx = __float2bfloat16_rn(v.x), hy = __float2bfloat16_rn(v.y);
    __nv_bfloat16 hz = __float2bfloat16_rn(v.z), hw = __float2bfloat16_rn(v.w);
    __nv_bfloat16 lx = __float2bfloat16_rn(v.x - __bfloat162float(hx));
    __nv_bfloat16 ly = __float2bfloat16_rn(v.y - __bfloat162float(hy));
    __nv_bfloat16 lz = __float2bfloat16_rn(v.z - __bfloat162float(hz));
    __nv_bfloat16 lw = __float2bfloat16_rn(v.w - __bfloat162float(hw));
    *(__nv_bfloat162*)(g_ehi + base)     = __nv_bfloat162(hx, hy);
    *(__nv_bfloat162*)(g_ehi + base + 2) = __nv_bfloat162(hz, hw);
    *(__nv_bfloat162*)(g_elo + base)     = __nv_bfloat162(lx, ly);
    *(__nv_bfloat162*)(g_elo + base + 2) = __nv_bfloat162(lz, lw);

    __syncthreads();
    for (int off = 64; off; off >>= 1) {
        if (tid < off) red[tid] += red[tid + off];
        __syncthreads();
    }
    if (tid == 0) {
        g_en[k] = red[0];
        g_counts[k] = 0;
        if (k == 0) g_nflag = 0;
    }
}

// ---------------------------------------------------------------------------
// GEMM2 via mma.sync bf16 + ldmatrix fragments, virtual K = 1536 (3 phases),
// 2-stage cp.async pipeline, fused in-register top-2 argmin.
// ---------------------------------------------------------------------------
#define SPITCH 72                       // bf16/row (64 data + 8 pad), 144B
#define STAGE_BYTES (128 * SPITCH * 2)  // 18432 per tile
#define NSTEP 384                       // 16 nt * 24 vc

__global__ __launch_bounds__(256, 2)
void gemm2_mma_kernel()
{
    extern __shared__ __align__(16) char dsm[];
    const uint32_t smem_u32 = (uint32_t)__cvta_generic_to_shared(dsm);

    const int tid  = threadIdx.x;
    const int lane = tid & 31;
    const int w    = tid >> 5;
    const int wm   = w >> 2;        // 0..1
    const int wn   = w & 3;         // 0..3
    const int lq   = lane >> 2;
    const int lr   = lane & 3;
    const int m0   = blockIdx.x * 128;

    // cp.async per-thread load coords
    const int lrow0 = tid >> 3;
    const int lch   = tid & 7;

    // ldmatrix per-thread byte offsets (relative to tile base)
    // A: x4 per mt -> 16x16 fragment
    const int arow  = (lane < 16) ? lane : (lane - 16);
    const int acol8 = (lane < 16) ? 0 : 8;
    uint32_t aoff[4];
#pragma unroll
    for (int mt = 0; mt < 4; mt++)
        aoff[mt] = (uint32_t)(((wm * 64 + mt * 16 + arow) * SPITCH + acol8) * 2);
    // B: x4 per pair p -> nn=2p,2p+1
    const int bg = lane >> 3;
    uint32_t boff[2];
#pragma unroll
    for (int p = 0; p < 2; p++) {
        int nrow = wn * 32 + (2 * p + (bg >> 1)) * 8 + (lane & 7);
        boff[p] = (uint32_t)((nrow * SPITCH + (bg & 1) * 8) * 2);
    }

    float v1[8], v2[8]; int i1[8];
#pragma unroll
    for (int s = 0; s < 8; s++) { v1[s] = 3.4e38f; v2[s] = 3.4e38f; i1[s] = 0; }

#define UPD(sl, cc, ss) do { float _s = (ss); \
    if (_s < v1[sl]) { v2[sl] = v1[sl]; v1[sl] = _s; i1[sl] = (cc); } \
    else if (_s < v2[sl]) v2[sl] = _s; } while (0)

    auto load_step = [&](int step, int stage) {
        const int nt    = step / 24;
        const int vc    = step - nt * 24;
        const int phase = vc >> 3;
        const int kk    = (vc & 7) * 64;
        const int n0    = nt * 128;
        const __nv_bfloat16* Ag = (phase < 2)  ? g_hhi : g_hlo;
        const __nv_bfloat16* Bg = (phase == 1) ? g_elo : g_ehi;
        uint32_t sAb = smem_u32 + stage * 2 * STAGE_BYTES;
        uint32_t sBb = sAb + STAGE_BYTES;
#pragma unroll
        for (int i = 0; i < 4; i++) {
            int r = lrow0 + i * 32;
            size_t goA = (size_t)(m0 + r) * D_DIM + kk + lch * 8;
            size_t goB = (size_t)(n0 + r) * D_DIM + kk + lch * 8;
            cp16(sAb + (uint32_t)((r * SPITCH + lch * 8) * 2), Ag + goA);
            cp16(sBb + (uint32_t)((r * SPITCH + lch * 8) * 2), Bg + goB);
        }
    };

    load_step(0, 0);
    CP_COMMIT();

    float acc[4][4][4];
    for (int nt = 0; nt < 16; nt++) {
        const int n0 = nt * 128;
#pragma unroll
        for (int a = 0; a < 4; a++)
#pragma unroll
            for (int b = 0; b < 4; b++)
#pragma unroll
                for (int c = 0; c < 4; c++) acc[a][b][c] = 0.0f;

        for (int vc = 0; vc < 24; vc++) {
            const int cur = nt * 24 + vc;
            if (cur + 1 < NSTEP) {
                load_step(cur + 1, (cur + 1) & 1);
                CP_COMMIT();
                CP_WAIT(1);
            } else {
                CP_WAIT(0);
            }
            __syncthreads();

            const uint32_t sAu = smem_u32 + (uint32_t)((cur & 1) * 2 * STAGE_BYTES);
            const uint32_t sBu = sAu + STAGE_BYTES;
#pragma unroll
            for (int ks = 0; ks < 4; ks++) {
                uint32_t bfr[4][2];
                {
                    uint32_t t0[4], t1[4];
                    ldsm_x4(t0, sBu + boff[0] + ks * 32);
                    ldsm_x4(t1, sBu + boff[1] + ks * 32);
                    bfr[0][0] = t0[0]; bfr[0][1] = t0[1];
                    bfr[1][0] = t0[2]; bfr[1][1] = t0[3];
                    bfr[2][0] = t1[0]; bfr[2][1] = t1[1];
                    bfr[3][0] = t1[2]; bfr[3][1] = t1[3];
                }
#pragma unroll
                for (int mt = 0; mt < 4; mt++) {
                    uint32_t afr[4];
                    ldsm_x4(afr, sAu + aoff[mt] + ks * 32);
#pragma unroll
                    for (int nn = 0; nn < 4; nn++)
                        mma16816(acc[mt][nn], afr, bfr[nn]);
                }
            }
            __syncthreads();
        }

        // fused score + top-2 update for this n-tile
#pragma unroll
        for (int mt = 0; mt < 4; mt++) {
#pragma unroll
            for (int nn = 0; nn < 4; nn++) {
                const int col = n0 + wn * 32 + nn * 8 + lr * 2;
                const float e0 = g_en[col], e1 = g_en[col + 1];
                const int s0 = mt * 2, s1 = mt * 2 + 1;
                UPD(s0, col,     e0 - 2.0f * acc[mt][nn][0]);
                UPD(s0, col + 1, e1 - 2.0f * acc[mt][nn][1]);
                UPD(s1, col,     e0 - 2.0f * acc[mt][nn][2]);
                UPD(s1, col + 1, e1 - 2.0f * acc[mt][nn][3]);
            }
        }
    }

    // reduce across the 4 lanes (lr) sharing each row
#pragma unroll
    for (int off = 1; off <= 2; off <<= 1) {
#pragma unroll
        for (int sl = 0; sl < 8; sl++) {
            float ov1 = __shfl_xor_sync(0xffffffffu, v1[sl], off);
            int   oi1 = __shfl_xor_sync(0xffffffffu, i1[sl], off);
            float ov2 = __shfl_xor_sync(0xffffffffu, v2[sl], off);
            if (ov1 < v1[sl] || (ov1 == v1[sl] && oi1 < i1[sl])) {
                v2[sl] = fminf(v1[sl], ov2); v1[sl] = ov1; i1[sl] = oi1;
            } else {
                v2[sl] = fminf(v2[sl], ov1);
            }
        }
    }

    // cross-warp (wn) reduction through smem overlay
    __syncthreads();
    float* rv1 = (float*)dsm;
    int*   ri1 = (int*)(dsm + 2048);
    float* rv2 = (float*)(dsm + 4096);
    if (lr == 0) {
#pragma unroll
        for (int sl = 0; sl < 8; sl++) {
            int row = wm * 64 + (sl >> 1) * 16 + (sl & 1) * 8 + lq;
            rv1[row * 4 + wn] = v1[sl];
            ri1[row * 4 + wn] = i1[sl];
            rv2[row * 4 + wn] = v2[sl];
        }
    }
    __syncthreads();
    if (tid < 128) {
        float bv1 = rv1[tid * 4]; int bi1 = ri1[tid * 4]; float bv2 = rv2[tid * 4];
#pragma unroll
        for (int j = 1; j < 4; j++) {
            float ov1 = rv1[tid * 4 + j]; int oi1 = ri1[tid * 4 + j]; float ov2 = rv2[tid * 4 + j];
            if (ov1 < bv1 || (ov1 == bv1 && oi1 < bi1)) {
                bv2 = fminf(bv1, ov2); bv1 = ov1; bi1 = oi1;
            } else {
                bv2 = fminf(bv2, ov1);
            }
        }
        const int row = m0 + tid;
        if (bv2 - bv1 <= MARGIN) {
            g_idx[row]  = -1;                 // sentinel: resolved by fallback
            g_best[row] = 0xFFFFFFFFFFFFFFFFull;
            int slot = atomicAdd(&g_nflag, 1);
            g_flagged[slot] = row;
        } else {
            g_idx[row] = bi1;
        }
    }
}

// ---------------------------------------------------------------------------
// Fallback: exact fp32 argmin for flagged rows. 8 blocks per row, one code
// per thread, combined via order-preserving packed atomicMin (ties -> lowest
// index, matching reference argmin).
// ---------------------------------------------------------------------------
__global__ __launch_bounds__(256)
void fallback_kernel(const float* __restrict__ emb)
{
    __shared__ float hrow[D_DIM];
    const int tid = threadIdx.x;
    const int cnt = g_nflag;
    const int total = cnt * 8;

    for (int wk = blockIdx.x; wk < total; wk += gridDim.x) {
        const int f     = wk >> 3;
        const int chunk = wk & 7;
        const int row   = g_flagged[f];

        if (tid < 128)
            *(float4*)(hrow + tid * 4) = *(const float4*)(g_h + (size_t)row * D_DIM + tid * 4);
        __syncthreads();

        const int k = chunk * 256 + tid;
        const float4* ep = (const float4*)(emb + (size_t)k * D_DIM);
        float a0 = 0.f, a1 = 0.f, a2 = 0.f, a3 = 0.f;
#pragma unroll 16
        for (int d4 = 0; d4 < D_DIM / 4; d4++) {
            float4 e = ep[d4];
            float4 h = *(const float4*)(hrow + d4 * 4);
            a0 += e.x * h.x; a1 += e.y * h.y; a2 += e.z * h.z; a3 += e.w * h.w;
        }
        float s = g_en[k] - 2.0f * ((a0 + a1) + (a2 + a3));
        unsigned long long key = ((unsigned long long)fmap(s) << 32) | (unsigned)k;
        atomicMin(&g_best[row], key);
        __syncthreads();
    }
}

// ---------------------------------------------------------------------------
// Epilogue per row: q_out, encodings, loss partial, counts
// ---------------------------------------------------------------------------
__global__ void epilogue_kernel(const float* __restrict__ emb, float* __restrict__ out)
{
    __shared__ float red[128];
    const int n   = blockIdx.x;
    const int tid = threadIdx.x;
    int idx = g_idx[n];
    if (idx < 0) idx = (int)(g_best[n] & 0xFFFFFFFFull);

    float4 hv = *(const float4*)(g_h + (size_t)n * D_DIM + tid * 4);
    float4 qv = *(const float4*)(emb + (size_t)idx * D_DIM + tid * 4);
    float d0 = qv.x - hv.x, d1 = qv.y - hv.y, d2 = qv.z - hv.z, d3 = qv.w - hv.w;

    float* qo = out + OFF_QOUT + (size_t)n * D_DIM + tid * 4;
    qo[0] = hv.x + d0; qo[1] = hv.y + d1; qo[2] = hv.z + d2; qo[3] = hv.w + d3;

    red[tid] = d0 * d0 + d1 * d1 + d2 * d2 + d3 * d3;

    float2* er2 = (float2*)(out + OFF_ENC + (size_t)n * K_CODES);
    const int unit = idx >> 1, comp = idx & 1;
#pragma unroll
    for (int i = 0; i < 8; i++) {
        int u = tid + i * 128;
        float2 v = make_float2(0.0f, 0.0f);
        if (u == unit) { if (comp == 0) v.x = 1.0f; else v.y = 1.0f; }
        er2[u] = v;
    }

    __syncthreads();
    for (int off = 64; off; off >>= 1) {
        if (tid < off) red[tid] += red[tid + off];
        __syncthreads();
    }
    if (tid == 0) {
        g_partial[n] = red[0];
        atomicAdd(&g_counts[idx], 1);
    }
}

// ---------------------------------------------------------------------------
__global__ void final_kernel(float* __restrict__ out)
{
    __shared__ float red[1024];
    const int tid = threadIdx.x;

    float s = 0.0f;
    for (int i = 0; i < N_ROWS / 1024; i++) s += g_partial[tid + i * 1024];
    red[tid] = s;
    __syncthreads();
    for (int off = 512; off; off >>= 1) {
        if (tid < off) red[tid] += red[tid + off];
        __syncthreads();
    }
    if (tid == 0) out[0] = 0.25f * red[0] / (float)((size_t)N_ROWS * D_DIM);
    __syncthreads();

    float p = 0.0f;
    for (int i = 0; i < K_CODES / 1024; i++) {
        float c  = (float)g_counts[tid + i * 1024];
        float pr = c * (1.0f / (float)N_ROWS);
        p += pr * logf(pr + 1e-10f);
    }
    red[tid] = p;
    __syncthreads();
    for (int off = 512; off; off >>= 1) {
        if (tid < off) red[tid] += red[tid + off];
        __syncthreads();
    }
    if (tid == 0) out[OFF_PERP] = expf(-red[0]);
}

// ---------------------------------------------------------------------------
extern "C" void kernel_launch(void* const* d_in, const int* in_sizes, int n_in,
                              void* d_out, int out_size)
{
    const float *x0 = nullptr, *x1 = nullptr, *W = nullptr, *b = nullptr, *emb = nullptr;
    for (int i = 0; i < n_in; i++) {
        const float* p = (const float*)d_in[i];
        const long long s = in_sizes[i];
        if (s == (long long)N_ROWS * HALFW)       { if (!x0) x0 = p; else x1 = p; }
        else if (s == (long long)D_DIM * D_DIM)   W = p;
        else if (s == (long long)D_DIM)           b = p;
        else if (s == (long long)K_CODES * D_DIM) emb = p;
    }
    float* out = (float*)d_out;

    static int smem_set = 0;
    if (!smem_set) {
        cudaFuncSetAttribute(gemm2_mma_kernel,
                             cudaFuncAttributeMaxDynamicSharedMemorySize,
                             4 * STAGE_BYTES);
        smem_set = 1;
    }

    gemm1_kernel<<<dim3(D_DIM / 128, N_ROWS / 128), 256>>>(x0, x1, W, b);
    prep_emb_kernel<<<K_CODES, 128>>>(emb);
    gemm2_mma_kernel<<<N_ROWS / 128, 256, 4 * STAGE_BYTES>>>();
    fallback_kernel<<<2048, 256>>>(emb);
    epilogue_kernel<<<N_ROWS, 128>>>(emb, out);
    final_kernel<<<1, 1024>>>(out);
}

// round 6
// speedup vs baseline: 2.2206x; 1.1193x over previous
#include <cuda_runtime.h>
#include <cuda_bf16.h>
#include <math.h>
#include <stdint.h>

// Problem constants
#define N_ROWS  32768
#define D_DIM   512
#define K_CODES 2048
#define HALFW   256

// Output layout: [loss(1) | q_out(2*32768*256) | perplexity(1) | encodings(32768*2048)]
#define OFF_QOUT 1
#define OFF_PERP (1 + N_ROWS * D_DIM)
#define OFF_ENC  (2 + N_ROWS * D_DIM)

#define MARGIN 0.02f

// Scratch (device globals: allocation-free per harness rules)
__device__ float         g_h[(size_t)N_ROWS * D_DIM];
__device__ __nv_bfloat16 g_hhi[(size_t)N_ROWS * D_DIM];
__device__ __nv_bfloat16 g_hlo[(size_t)N_ROWS * D_DIM];
__device__ __nv_bfloat16 g_ehi[(size_t)K_CODES * D_DIM];
__device__ __nv_bfloat16 g_elo[(size_t)K_CODES * D_DIM];
__device__ __nv_bfloat16 g_x1[(size_t)N_ROWS * D_DIM];
__device__ __nv_bfloat16 g_x2[(size_t)N_ROWS * D_DIM];
__device__ __nv_bfloat16 g_x3[(size_t)N_ROWS * D_DIM];
__device__ __nv_bfloat16 g_w1[(size_t)D_DIM * D_DIM];
__device__ __nv_bfloat16 g_w2[(size_t)D_DIM * D_DIM];
__device__ float g_en[K_CODES];
__device__ int   g_idx[N_ROWS];
__device__ float g_partial[N_ROWS];
__device__ int   g_counts[K_CODES];
__device__ int   g_nflag;
__device__ int   g_flagged[N_ROWS];
__device__ unsigned long long g_best[N_ROWS];

// ---------------------------------------------------------------------------
// PTX helpers
// ---------------------------------------------------------------------------
__device__ __forceinline__ void mma16816(float* c, const uint32_t* a, const uint32_t* b) {
    asm volatile(
        "mma.sync.aligned.m16n8k16.row.col.f32.bf16.bf16.f32 "
        "{%0,%1,%2,%3}, {%4,%5,%6,%7}, {%8,%9}, {%0,%1,%2,%3};"
        : "+f"(c[0]), "+f"(c[1]), "+f"(c[2]), "+f"(c[3])
        : "r"(a[0]), "r"(a[1]), "r"(a[2]), "r"(a[3]), "r"(b[0]), "r"(b[1]));
}
__device__ __forceinline__ void ldsm_x4(uint32_t* r, uint32_t addr) {
    asm volatile("ldmatrix.sync.aligned.m8n8.x4.shared.b16 {%0,%1,%2,%3}, [%4];"
                 : "=r"(r[0]), "=r"(r[1]), "=r"(r[2]), "=r"(r[3]) : "r"(addr));
}
__device__ __forceinline__ void cp16(uint32_t dst_smem, const void* src) {
    asm volatile("cp.async.cg.shared.global [%0], [%1], 16;" :: "r"(dst_smem), "l"(src));
}
#define CP_COMMIT() asm volatile("cp.async.commit_group;" ::: "memory")
#define CP_WAIT(N)  asm volatile("cp.async.wait_group %0;" :: "n"(N) : "memory")

__device__ __forceinline__ uint32_t fmap(float f) {  // order-preserving float->uint
    uint32_t u = __float_as_uint(f);
    return (u & 0x80000000u) ? ~u : (u | 0x80000000u);
}

#define SPITCH 72                       // bf16/row (64 data + 8 pad), 144B
#define STAGE_BYTES (128 * SPITCH * 2)  // 18432 per tile

// ---------------------------------------------------------------------------
// prep_x: concat(x0,x1) -> 3-way bf16 split (X1+X2+X3 ~ x to ~2^-27 rel)
// ---------------------------------------------------------------------------
__global__ void prep_x_kernel(const float* __restrict__ x0, const float* __restrict__ x1)
{
    const size_t i = ((size_t)blockIdx.x * 256 + threadIdx.x) * 4;  // elem idx in [N,512]
    const int col = (int)(i & (D_DIM - 1));
    const size_t row = i >> 9;
    const float* src = (col < HALFW) ? (x0 + row * HALFW + col)
                                     : (x1 + row * HALFW + (col - HALFW));
    float4 v = *(const float4*)src;
    float e[4] = {v.x, v.y, v.z, v.w};
    __nv_bfloat16 a[4], b[4], c[4];
#pragma unroll
    for (int j = 0; j < 4; j++) {
        a[j] = __float2bfloat16_rn(e[j]);
        float r1 = e[j] - __bfloat162float(a[j]);
        b[j] = __float2bfloat16_rn(r1);
        float r2 = r1 - __bfloat162float(b[j]);
        c[j] = __float2bfloat16_rn(r2);
    }
    *(__nv_bfloat162*)(g_x1 + i)     = __nv_bfloat162(a[0], a[1]);
    *(__nv_bfloat162*)(g_x1 + i + 2) = __nv_bfloat162(a[2], a[3]);
    *(__nv_bfloat162*)(g_x2 + i)     = __nv_bfloat162(b[0], b[1]);
    *(__nv_bfloat162*)(g_x2 + i + 2) = __nv_bfloat162(b[2], b[3]);
    *(__nv_bfloat162*)(g_x3 + i)     = __nv_bfloat162(c[0], c[1]);
    *(__nv_bfloat162*)(g_x3 + i + 2) = __nv_bfloat162(c[2], c[3]);
}

// prep_w: W -> 2-way bf16 split
__global__ void prep_w_kernel(const float* __restrict__ W)
{
    const size_t i = ((size_t)blockIdx.x * 256 + threadIdx.x) * 4;
    float4 v = *(const float4*)(W + i);
    float e[4] = {v.x, v.y, v.z, v.w};
    __nv_bfloat16 a[4], b[4];
#pragma unroll
    for (int j = 0; j < 4; j++) {
        a[j] = __float2bfloat16_rn(e[j]);
        b[j] = __float2bfloat16_rn(e[j] - __bfloat162float(a[j]));
    }
    *(__nv_bfloat162*)(g_w1 + i)     = __nv_bfloat162(a[0], a[1]);
    *(__nv_bfloat162*)(g_w1 + i + 2) = __nv_bfloat162(a[2], a[3]);
    *(__nv_bfloat162*)(g_w2 + i)     = __nv_bfloat162(b[0], b[1]);
    *(__nv_bfloat162*)(g_w2 + i + 2) = __nv_bfloat162(b[2], b[3]);
}

// ---------------------------------------------------------------------------
// GEMM1 via mma.sync bf16 5-phase: X1W1, X1W2, X2W1, X2W2, X3W1
// (error ~ X3*W2 ~ 1e-9 rel — below fp32 reorder noise).
// CTA: 128 rows x 128 cols; virtual K = 5 * 512 = 40 chunks of 64.
// Epilogue: + bias, write g_h fp32 and hhi/hlo bf16 splits.
// ---------------------------------------------------------------------------
#define NSTEP1 40

__global__ __launch_bounds__(256, 2)
void gemm1_mma_kernel(const float* __restrict__ bias)
{
    extern __shared__ __align__(16) char dsm[];
    const uint32_t smem_u32 = (uint32_t)__cvta_generic_to_shared(dsm);

    const int tid  = threadIdx.x;
    const int lane = tid & 31;
    const int w    = tid >> 5;
    const int wm   = w >> 2;
    const int wn   = w & 3;
    const int lq   = lane >> 2;
    const int lr   = lane & 3;
    const int m0   = blockIdx.y * 128;
    const int n0   = blockIdx.x * 128;

    const int lrow0 = tid >> 3;
    const int lch   = tid & 7;

    const int arow  = (lane < 16) ? lane : (lane - 16);
    const int acol8 = (lane < 16) ? 0 : 8;
    uint32_t aoff[4];
#pragma unroll
    for (int mt = 0; mt < 4; mt++)
        aoff[mt] = (uint32_t)(((wm * 64 + mt * 16 + arow) * SPITCH + acol8) * 2);
    const int bg = lane >> 3;
    uint32_t boff[2];
#pragma unroll
    for (int p = 0; p < 2; p++) {
        int nrow = wn * 32 + (2 * p + (bg >> 1)) * 8 + (lane & 7);
        boff[p] = (uint32_t)((nrow * SPITCH + (bg & 1) * 8) * 2);
    }

    auto load_step = [&](int step, int stage) {
        const int phase = step >> 3;        // 0..4
        const int kk    = (step & 7) * 64;
        const __nv_bfloat16* Ag = (phase < 2) ? g_x1 : (phase < 4 ? g_x2 : g_x3);
        const __nv_bfloat16* Bg = (phase & 1) ? g_w2 : g_w1;
        uint32_t sAb = smem_u32 + stage * 2 * STAGE_BYTES;
        uint32_t sBb = sAb + STAGE_BYTES;
#pragma unroll
        for (int i = 0; i < 4; i++) {
            int r = lrow0 + i * 32;
            size_t goA = (size_t)(m0 + r) * D_DIM + kk + lch * 8;
            size_t goB = (size_t)(n0 + r) * D_DIM + kk + lch * 8;
            cp16(sAb + (uint32_t)((r * SPITCH + lch * 8) * 2), Ag + goA);
            cp16(sBb + (uint32_t)((r * SPITCH + lch * 8) * 2), Bg + goB);
        }
    };

    float acc[4][4][4];
#pragma unroll
    for (int a = 0; a < 4; a++)
#pragma unroll
        for (int b = 0; b < 4; b++)
#pragma unroll
            for (int c = 0; c < 4; c++) acc[a][b][c] = 0.0f;

    load_step(0, 0);
    CP_COMMIT();

    for (int cur = 0; cur < NSTEP1; cur++) {
        if (cur + 1 < NSTEP1) {
            load_step(cur + 1, (cur + 1) & 1);
            CP_COMMIT();
            CP_WAIT(1);
        } else {
            CP_WAIT(0);
        }
        __syncthreads();

        const uint32_t sAu = smem_u32 + (uint32_t)((cur & 1) * 2 * STAGE_BYTES);
        const uint32_t sBu = sAu + STAGE_BYTES;
#pragma unroll
        for (int ks = 0; ks < 4; ks++) {
            uint32_t bfr[4][2];
            {
                uint32_t t0[4], t1[4];
                ldsm_x4(t0, sBu + boff[0] + ks * 32);
                ldsm_x4(t1, sBu + boff[1] + ks * 32);
                bfr[0][0] = t0[0]; bfr[0][1] = t0[1];
                bfr[1][0] = t0[2]; bfr[1][1] = t0[3];
                bfr[2][0] = t1[0]; bfr[2][1] = t1[1];
                bfr[3][0] = t1[2]; bfr[3][1] = t1[3];
            }
#pragma unroll
            for (int mt = 0; mt < 4; mt++) {
                uint32_t afr[4];
                ldsm_x4(afr, sAu + aoff[mt] + ks * 32);
#pragma unroll
                for (int nn = 0; nn < 4; nn++)
                    mma16816(acc[mt][nn], afr, bfr[nn]);
            }
        }
        __syncthreads();
    }

    // epilogue: bias + store h (fp32) and hi/lo bf16 splits
    float bia[4][2];
#pragma unroll
    for (int nn = 0; nn < 4; nn++) {
        int col = n0 + wn * 32 + nn * 8 + lr * 2;
        bia[nn][0] = bias[col];
        bia[nn][1] = bias[col + 1];
    }
#pragma unroll
    for (int mt = 0; mt < 4; mt++) {
#pragma unroll
        for (int half = 0; half < 2; half++) {
            const int row = m0 + wm * 64 + mt * 16 + half * 8 + lq;
#pragma unroll
            for (int nn = 0; nn < 4; nn++) {
                const int col = n0 + wn * 32 + nn * 8 + lr * 2;
                float h0 = acc[mt][nn][half * 2 + 0] + bia[nn][0];
                float h1 = acc[mt][nn][half * 2 + 1] + bia[nn][1];
                const size_t o = (size_t)row * D_DIM + col;
                *(float2*)(g_h + o) = make_float2(h0, h1);
                __nv_bfloat16 p0 = __float2bfloat16_rn(h0);
                __nv_bfloat16 p1 = __float2bfloat16_rn(h1);
                __nv_bfloat16 q0 = __float2bfloat16_rn(h0 - __bfloat162float(p0));
                __nv_bfloat16 q1 = __float2bfloat16_rn(h1 - __bfloat162float(p1));
                *(__nv_bfloat162*)(g_hhi + o) = __nv_bfloat162(p0, p1);
                *(__nv_bfloat162*)(g_hlo + o) = __nv_bfloat162(q0, q1);
            }
        }
    }
}

// ---------------------------------------------------------------------------
// prep_emb: ||e_k||^2 (fp32 exact), e -> bf16 hi/lo split, zero counts/nflag
// ---------------------------------------------------------------------------
__global__ void prep_emb_kernel(const float* __restrict__ emb)
{
    __shared__ float red[128];
    const int k   = blockIdx.x;
    const int tid = threadIdx.x;
    const size_t base = (size_t)k * D_DIM + tid * 4;
    float4 v = *(const float4*)(emb + base);
    red[tid] = v.x * v.x + v.y * v.y + v.z * v.z + v.w * v.w;

    __nv_bfloat16 hx = __float2bfloat16_rn(v.x), hy = __float2bfloat16_rn(v.y);
    __nv_bfloat16 hz = __float2bfloat16_rn(v.z), hw = __float2bfloat16_rn(v.w);
    __nv_bfloat16 lx = __float2bfloat16_rn(v.x - __bfloat162float(hx));
    __nv_bfloat16 ly = __float2bfloat16_rn(v.y - __bfloat162float(hy));
    __nv_bfloat16 lz = __float2bfloat16_rn(v.z - __bfloat162float(hz));
    __nv_bfloat16 lw = __float2bfloat16_rn(v.w - __bfloat162float(hw));
    *(__nv_bfloat162*)(g_ehi + base)     = __nv_bfloat162(hx, hy);
    *(__nv_bfloat162*)(g_ehi + base + 2) = __nv_bfloat162(hz, hw);
    *(__nv_bfloat162*)(g_elo + base)     = __nv_bfloat162(lx, ly);
    *(__nv_bfloat162*)(g_elo + base + 2) = __nv_bfloat162(lz, lw);

    __syncthreads();
    for (int off = 64; off; off >>= 1) {
        if (tid < off) red[tid] += red[tid + off];
        __syncthreads();
    }
    if (tid == 0) {
        g_en[k] = red[0];
        g_counts[k] = 0;
        if (k == 0) g_nflag = 0;
    }
}

// ---------------------------------------------------------------------------
// GEMM2 via mma.sync bf16 + ldmatrix, virtual K = 1536 (3 phases), 2-stage
// cp.async pipeline, fused in-register top-2 argmin.
// ---------------------------------------------------------------------------
#define NSTEP 384

__global__ __launch_bounds__(256, 2)
void gemm2_mma_kernel()
{
    extern __shared__ __align__(16) char dsm[];
    const uint32_t smem_u32 = (uint32_t)__cvta_generic_to_shared(dsm);

    const int tid  = threadIdx.x;
    const int lane = tid & 31;
    const int w    = tid >> 5;
    const int wm   = w >> 2;
    const int wn   = w & 3;
    const int lq   = lane >> 2;
    const int lr   = lane & 3;
    const int m0   = blockIdx.x * 128;

    const int lrow0 = tid >> 3;
    const int lch   = tid & 7;

    const int arow  = (lane < 16) ? lane : (lane - 16);
    const int acol8 = (lane < 16) ? 0 : 8;
    uint32_t aoff[4];
#pragma unroll
    for (int mt = 0; mt < 4; mt++)
        aoff[mt] = (uint32_t)(((wm * 64 + mt * 16 + arow) * SPITCH + acol8) * 2);
    const int bg = lane >> 3;
    uint32_t boff[2];
#pragma unroll
    for (int p = 0; p < 2; p++) {
        int nrow = wn * 32 + (2 * p + (bg >> 1)) * 8 + (lane & 7);
        boff[p] = (uint32_t)((nrow * SPITCH + (bg & 1) * 8) * 2);
    }

    float v1[8], v2[8]; int i1[8];
#pragma unroll
    for (int s = 0; s < 8; s++) { v1[s] = 3.4e38f; v2[s] = 3.4e38f; i1[s] = 0; }

#define UPD(sl, cc, ss) do { float _s = (ss); \
    if (_s < v1[sl]) { v2[sl] = v1[sl]; v1[sl] = _s; i1[sl] = (cc); } \
    else if (_s < v2[sl]) v2[sl] = _s; } while (0)

    auto load_step = [&](int step, int stage) {
        const int nt    = step / 24;
        const int vc    = step - nt * 24;
        const int phase = vc >> 3;
        const int kk    = (vc & 7) * 64;
        const int n0    = nt * 128;
        const __nv_bfloat16* Ag = (phase < 2)  ? g_hhi : g_hlo;
        const __nv_bfloat16* Bg = (phase == 1) ? g_elo : g_ehi;
        uint32_t sAb = smem_u32 + stage * 2 * STAGE_BYTES;
        uint32_t sBb = sAb + STAGE_BYTES;
#pragma unroll
        for (int i = 0; i < 4; i++) {
            int r = lrow0 + i * 32;
            size_t goA = (size_t)(m0 + r) * D_DIM + kk + lch * 8;
            size_t goB = (size_t)(n0 + r) * D_DIM + kk + lch * 8;
            cp16(sAb + (uint32_t)((r * SPITCH + lch * 8) * 2), Ag + goA);
            cp16(sBb + (uint32_t)((r * SPITCH + lch * 8) * 2), Bg + goB);
        }
    };

    load_step(0, 0);
    CP_COMMIT();

    float acc[4][4][4];
    for (int nt = 0; nt < 16; nt++) {
        const int n0 = nt * 128;
#pragma unroll
        for (int a = 0; a < 4; a++)
#pragma unroll
            for (int b = 0; b < 4; b++)
#pragma unroll
                for (int c = 0; c < 4; c++) acc[a][b][c] = 0.0f;

        for (int vc = 0; vc < 24; vc++) {
            const int cur = nt * 24 + vc;
            if (cur + 1 < NSTEP) {
                load_step(cur + 1, (cur + 1) & 1);
                CP_COMMIT();
                CP_WAIT(1);
            } else {
                CP_WAIT(0);
            }
            __syncthreads();

            const uint32_t sAu = smem_u32 + (uint32_t)((cur & 1) * 2 * STAGE_BYTES);
            const uint32_t sBu = sAu + STAGE_BYTES;
#pragma unroll
            for (int ks = 0; ks < 4; ks++) {
                uint32_t bfr[4][2];
                {
                    uint32_t t0[4], t1[4];
                    ldsm_x4(t0, sBu + boff[0] + ks * 32);
                    ldsm_x4(t1, sBu + boff[1] + ks * 32);
                    bfr[0][0] = t0[0]; bfr[0][1] = t0[1];
                    bfr[1][0] = t0[2]; bfr[1][1] = t0[3];
                    bfr[2][0] = t1[0]; bfr[2][1] = t1[1];
                    bfr[3][0] = t1[2]; bfr[3][1] = t1[3];
                }
#pragma unroll
                for (int mt = 0; mt < 4; mt++) {
                    uint32_t afr[4];
                    ldsm_x4(afr, sAu + aoff[mt] + ks * 32);
#pragma unroll
                    for (int nn = 0; nn < 4; nn++)
                        mma16816(acc[mt][nn], afr, bfr[nn]);
                }
            }
            __syncthreads();
        }

#pragma unroll
        for (int mt = 0; mt < 4; mt++) {
#pragma unroll
            for (int nn = 0; nn < 4; nn++) {
                const int col = n0 + wn * 32 + nn * 8 + lr * 2;
                const float e0 = g_en[col], e1 = g_en[col + 1];
                const int s0 = mt * 2, s1 = mt * 2 + 1;
                UPD(s0, col,     e0 - 2.0f * acc[mt][nn][0]);
                UPD(s0, col + 1, e1 - 2.0f * acc[mt][nn][1]);
                UPD(s1, col,     e0 - 2.0f * acc[mt][nn][2]);
                UPD(s1, col + 1, e1 - 2.0f * acc[mt][nn][3]);
            }
        }
    }

#pragma unroll
    for (int off = 1; off <= 2; off <<= 1) {
#pragma unroll
        for (int sl = 0; sl < 8; sl++) {
            float ov1 = __shfl_xor_sync(0xffffffffu, v1[sl], off);
            int   oi1 = __shfl_xor_sync(0xffffffffu, i1[sl], off);
            float ov2 = __shfl_xor_sync(0xffffffffu, v2[sl], off);
            if (ov1 < v1[sl] || (ov1 == v1[sl] && oi1 < i1[sl])) {
                v2[sl] = fminf(v1[sl], ov2); v1[sl] = ov1; i1[sl] = oi1;
            } else {
                v2[sl] = fminf(v2[sl], ov1);
            }
        }
    }

    __syncthreads();
    float* rv1 = (float*)dsm;
    int*   ri1 = (int*)(dsm + 2048);
    float* rv2 = (float*)(dsm + 4096);
    if (lr == 0) {
#pragma unroll
        for (int sl = 0; sl < 8; sl++) {
            int row = wm * 64 + (sl >> 1) * 16 + (sl & 1) * 8 + lq;
            rv1[row * 4 + wn] = v1[sl];
            ri1[row * 4 + wn] = i1[sl];
            rv2[row * 4 + wn] = v2[sl];
        }
    }
    __syncthreads();
    if (tid < 128) {
        float bv1 = rv1[tid * 4]; int bi1 = ri1[tid * 4]; float bv2 = rv2[tid * 4];
#pragma unroll
        for (int j = 1; j < 4; j++) {
            float ov1 = rv1[tid * 4 + j]; int oi1 = ri1[tid * 4 + j]; float ov2 = rv2[tid * 4 + j];
            if (ov1 < bv1 || (ov1 == bv1 && oi1 < bi1)) {
                bv2 = fminf(bv1, ov2); bv1 = ov1; bi1 = oi1;
            } else {
                bv2 = fminf(bv2, ov1);
            }
        }
        const int row = m0 + tid;
        if (bv2 - bv1 <= MARGIN) {
            g_idx[row]  = -1;
            g_best[row] = 0xFFFFFFFFFFFFFFFFull;
            int slot = atomicAdd(&g_nflag, 1);
            g_flagged[slot] = row;
        } else {
            g_idx[row] = bi1;
        }
    }
}

// ---------------------------------------------------------------------------
// Fallback: exact fp32 argmin for flagged rows; packed atomicMin combine.
// ---------------------------------------------------------------------------
__global__ __launch_bounds__(256)
void fallback_kernel(const float* __restrict__ emb)
{
    __shared__ float hrow[D_DIM];
    const int tid = threadIdx.x;
    const int cnt = g_nflag;
    const int total = cnt * 8;

    for (int wk = blockIdx.x; wk < total; wk += gridDim.x) {
        const int f     = wk >> 3;
        const int chunk = wk & 7;
        const int row   = g_flagged[f];

        if (tid < 128)
            *(float4*)(hrow + tid * 4) = *(const float4*)(g_h + (size_t)row * D_DIM + tid * 4);
        __syncthreads();

        const int k = chunk * 256 + tid;
        const float4* ep = (const float4*)(emb + (size_t)k * D_DIM);
        float a0 = 0.f, a1 = 0.f, a2 = 0.f, a3 = 0.f;
#pragma unroll 16
        for (int d4 = 0; d4 < D_DIM / 4; d4++) {
            float4 e = ep[d4];
            float4 h = *(const float4*)(hrow + d4 * 4);
            a0 += e.x * h.x; a1 += e.y * h.y; a2 += e.z * h.z; a3 += e.w * h.w;
        }
        float s = g_en[k] - 2.0f * ((a0 + a1) + (a2 + a3));
        unsigned long long key = ((unsigned long long)fmap(s) << 32) | (unsigned)k;
        atomicMin(&g_best[row], key);
        __syncthreads();
    }
}

// ---------------------------------------------------------------------------
// Epilogue per row: q_out, encodings, loss partial, counts
// ---------------------------------------------------------------------------
__global__ void epilogue_kernel(const float* __restrict__ emb, float* __restrict__ out)
{
    __shared__ float red[128];
    const int n   = blockIdx.x;
    const int tid = threadIdx.x;
    int idx = g_idx[n];
    if (idx < 0) idx = (int)(g_best[n] & 0xFFFFFFFFull);

    float4 hv = *(const float4*)(g_h + (size_t)n * D_DIM + tid * 4);
    float4 qv = *(const float4*)(emb + (size_t)idx * D_DIM + tid * 4);
    float d0 = qv.x - hv.x, d1 = qv.y - hv.y, d2 = qv.z - hv.z, d3 = qv.w - hv.w;

    float* qo = out + OFF_QOUT + (size_t)n * D_DIM + tid * 4;
    qo[0] = hv.x + d0; qo[1] = hv.y + d1; qo[2] = hv.z + d2; qo[3] = hv.w + d3;

    red[tid] = d0 * d0 + d1 * d1 + d2 * d2 + d3 * d3;

    float2* er2 = (float2*)(out + OFF_ENC + (size_t)n * K_CODES);
    const int unit = idx >> 1, comp = idx & 1;
#pragma unroll
    for (int i = 0; i < 8; i++) {
        int u = tid + i * 128;
        float2 v = make_float2(0.0f, 0.0f);
        if (u == unit) { if (comp == 0) v.x = 1.0f; else v.y = 1.0f; }
        er2[u] = v;
    }

    __syncthreads();
    for (int off = 64; off; off >>= 1) {
        if (tid < off) red[tid] += red[tid + off];
        __syncthreads();
    }
    if (tid == 0) {
        g_partial[n] = red[0];
        atomicAdd(&g_counts[idx], 1);
    }
}

// ---------------------------------------------------------------------------
__global__ void final_kernel(float* __restrict__ out)
{
    __shared__ float red[1024];
    const int tid = threadIdx.x;

    float s = 0.0f;
    for (int i = 0; i < N_ROWS / 1024; i++) s += g_partial[tid + i * 1024];
    red[tid] = s;
    __syncthreads();
    for (int off = 512; off; off >>= 1) {
        if (tid < off) red[tid] += red[tid + off];
        __syncthreads();
    }
    if (tid == 0) out[0] = 0.25f * red[0] / (float)((size_t)N_ROWS * D_DIM);
    __syncthreads();

    float p = 0.0f;
    for (int i = 0; i < K_CODES / 1024; i++) {
        float c  = (float)g_counts[tid + i * 1024];
        float pr = c * (1.0f / (float)N_ROWS);
        p += pr * logf(pr + 1e-10f);
    }
    red[tid] = p;
    __syncthreads();
    for (int off = 512; off; off >>= 1) {
        if (tid < off) red[tid] += red[tid + off];
        __syncthreads();
    }
    if (tid == 0) out[OFF_PERP] = expf(-red[0]);
}

// ---------------------------------------------------------------------------
extern "C" void kernel_launch(void* const* d_in, const int* in_sizes, int n_in,
                              void* d_out, int out_size)
{
    const float *x0 = nullptr, *x1 = nullptr, *W = nullptr, *b = nullptr, *emb = nullptr;
    for (int i = 0; i < n_in; i++) {
        const float* p = (const float*)d_in[i];
        const long long s = in_sizes[i];
        if (s == (long long)N_ROWS * HALFW)       { if (!x0) x0 = p; else x1 = p; }
        else if (s == (long long)D_DIM * D_DIM)   W = p;
        else if (s == (long long)D_DIM)           b = p;
        else if (s == (long long)K_CODES * D_DIM) emb = p;
    }
    float* out = (float*)d_out;

    static int smem_set = 0;
    if (!smem_set) {
        cudaFuncSetAttribute(gemm2_mma_kernel,
                             cudaFuncAttributeMaxDynamicSharedMemorySize, 4 * STAGE_BYTES);
        cudaFuncSetAttribute(gemm1_mma_kernel,
                             cudaFuncAttributeMaxDynamicSharedMemorySize, 4 * STAGE_BYTES);
        smem_set = 1;
    }

    prep_x_kernel<<<(N_ROWS * D_DIM) / 1024, 256>>>(x0, x1);
    prep_w_kernel<<<(D_DIM * D_DIM) / 1024, 256>>>(W);
    prep_emb_kernel<<<K_CODES, 128>>>(emb);
    gemm1_mma_kernel<<<dim3(D_DIM / 128, N_ROWS / 128), 256, 4 * STAGE_BYTES>>>(b);
    gemm2_mma_kernel<<<N_ROWS / 128, 256, 4 * STAGE_BYTES>>>();
    fallback_kernel<<<2048, 256>>>(emb);
    epilogue_kernel<<<N_ROWS, 128>>>(emb, out);
    final_kernel<<<1, 1024>>>(out);
}

// round 8
// speedup vs baseline: 2.2477x; 1.0122x over previous
#include <cuda_runtime.h>
#include <cuda_bf16.h>
#include <math.h>
#include <stdint.h>

// Problem constants
#define N_ROWS  32768
#define D_DIM   512
#define K_CODES 2048
#define HALFW   256

// Output layout: [loss(1) | q_out(2*32768*256) | perplexity(1) | encodings(32768*2048)]
#define OFF_QOUT 1
#define OFF_PERP (1 + N_ROWS * D_DIM)
#define OFF_ENC  (2 + N_ROWS * D_DIM)   // NOTE: only 8-byte aligned (idx ≡ 2 mod 4)

#define MARGIN 0.02f

// Scratch (device globals: allocation-free per harness rules)
__device__ float         g_h[(size_t)N_ROWS * D_DIM];
__device__ __nv_bfloat16 g_hhi[(size_t)N_ROWS * D_DIM];
__device__ __nv_bfloat16 g_hlo[(size_t)N_ROWS * D_DIM];
__device__ __nv_bfloat16 g_ehi[(size_t)K_CODES * D_DIM];
__device__ __nv_bfloat16 g_elo[(size_t)K_CODES * D_DIM];
__device__ __nv_bfloat16 g_x1[(size_t)N_ROWS * D_DIM];
__device__ __nv_bfloat16 g_x2[(size_t)N_ROWS * D_DIM];
__device__ __nv_bfloat16 g_x3[(size_t)N_ROWS * D_DIM];
__device__ __nv_bfloat16 g_w1[(size_t)D_DIM * D_DIM];
__device__ __nv_bfloat16 g_w2[(size_t)D_DIM * D_DIM];
__device__ float g_en[K_CODES];
__device__ int   g_idx[N_ROWS];
__device__ float g_partial[N_ROWS];
__device__ int   g_counts[K_CODES];
__device__ int   g_nflag;
__device__ int   g_flagged[N_ROWS];
__device__ unsigned long long g_best[N_ROWS];

// ---------------------------------------------------------------------------
// PTX helpers
// ---------------------------------------------------------------------------
__device__ __forceinline__ void mma16816(float* c, const uint32_t* a, const uint32_t* b) {
    asm volatile(
        "mma.sync.aligned.m16n8k16.row.col.f32.bf16.bf16.f32 "
        "{%0,%1,%2,%3}, {%4,%5,%6,%7}, {%8,%9}, {%0,%1,%2,%3};"
        : "+f"(c[0]), "+f"(c[1]), "+f"(c[2]), "+f"(c[3])
        : "r"(a[0]), "r"(a[1]), "r"(a[2]), "r"(a[3]), "r"(b[0]), "r"(b[1]));
}
__device__ __forceinline__ void ldsm_x4(uint32_t* r, uint32_t addr) {
    asm volatile("ldmatrix.sync.aligned.m8n8.x4.shared.b16 {%0,%1,%2,%3}, [%4];"
                 : "=r"(r[0]), "=r"(r[1]), "=r"(r[2]), "=r"(r[3]) : "r"(addr));
}
__device__ __forceinline__ void cp16(uint32_t dst_smem, const void* src) {
    asm volatile("cp.async.cg.shared.global [%0], [%1], 16;" :: "r"(dst_smem), "l"(src));
}
#define CP_COMMIT() asm volatile("cp.async.commit_group;" ::: "memory")
#define CP_WAIT(N)  asm volatile("cp.async.wait_group %0;" :: "n"(N) : "memory")

__device__ __forceinline__ uint32_t fmap(float f) {  // order-preserving float->uint
    uint32_t u = __float_as_uint(f);
    return (u & 0x80000000u) ? ~u : (u | 0x80000000u);
}

#define SPITCH 72                       // bf16/row (64 data + 8 pad), 144B
#define STAGE_BYTES (128 * SPITCH * 2)  // 18432 per tile

// ---------------------------------------------------------------------------
// prep_x: concat(x0,x1) -> 3-way bf16 split
// ---------------------------------------------------------------------------
__global__ void prep_x_kernel(const float* __restrict__ x0, const float* __restrict__ x1)
{
    const size_t i = ((size_t)blockIdx.x * 256 + threadIdx.x) * 4;
    const int col = (int)(i & (D_DIM - 1));
    const size_t row = i >> 9;
    const float* src = (col < HALFW) ? (x0 + row * HALFW + col)
                                     : (x1 + row * HALFW + (col - HALFW));
    float4 v = *(const float4*)src;
    float e[4] = {v.x, v.y, v.z, v.w};
    __nv_bfloat16 a[4], b[4], c[4];
#pragma unroll
    for (int j = 0; j < 4; j++) {
        a[j] = __float2bfloat16_rn(e[j]);
        float r1 = e[j] - __bfloat162float(a[j]);
        b[j] = __float2bfloat16_rn(r1);
        float r2 = r1 - __bfloat162float(b[j]);
        c[j] = __float2bfloat16_rn(r2);
    }
    *(__nv_bfloat162*)(g_x1 + i)     = __nv_bfloat162(a[0], a[1]);
    *(__nv_bfloat162*)(g_x1 + i + 2) = __nv_bfloat162(a[2], a[3]);
    *(__nv_bfloat162*)(g_x2 + i)     = __nv_bfloat162(b[0], b[1]);
    *(__nv_bfloat162*)(g_x2 + i + 2) = __nv_bfloat162(b[2], b[3]);
    *(__nv_bfloat162*)(g_x3 + i)     = __nv_bfloat162(c[0], c[1]);
    *(__nv_bfloat162*)(g_x3 + i + 2) = __nv_bfloat162(c[2], c[3]);
}

// prep_w: W -> 2-way bf16 split
__global__ void prep_w_kernel(const float* __restrict__ W)
{
    const size_t i = ((size_t)blockIdx.x * 256 + threadIdx.x) * 4;
    float4 v = *(const float4*)(W + i);
    float e[4] = {v.x, v.y, v.z, v.w};
    __nv_bfloat16 a[4], b[4];
#pragma unroll
    for (int j = 0; j < 4; j++) {
        a[j] = __float2bfloat16_rn(e[j]);
        b[j] = __float2bfloat16_rn(e[j] - __bfloat162float(a[j]));
    }
    *(__nv_bfloat162*)(g_w1 + i)     = __nv_bfloat162(a[0], a[1]);
    *(__nv_bfloat162*)(g_w1 + i + 2) = __nv_bfloat162(a[2], a[3]);
    *(__nv_bfloat162*)(g_w2 + i)     = __nv_bfloat162(b[0], b[1]);
    *(__nv_bfloat162*)(g_w2 + i + 2) = __nv_bfloat162(b[2], b[3]);
}

// ---------------------------------------------------------------------------
// GEMM1 via mma.sync bf16 5-phase: X1W1, X1W2, X2W1, X2W2, X3W1.
// Single-sync 2-stage cp.async pipeline.
// ---------------------------------------------------------------------------
#define NSTEP1 40

__global__ __launch_bounds__(256, 2)
void gemm1_mma_kernel(const float* __restrict__ bias)
{
    extern __shared__ __align__(16) char dsm[];
    const uint32_t smem_u32 = (uint32_t)__cvta_generic_to_shared(dsm);

    const int tid  = threadIdx.x;
    const int lane = tid & 31;
    const int w    = tid >> 5;
    const int wm   = w >> 2;
    const int wn   = w & 3;
    const int lq   = lane >> 2;
    const int lr   = lane & 3;
    const int m0   = blockIdx.y * 128;
    const int n0   = blockIdx.x * 128;

    const int lrow0 = tid >> 3;
    const int lch   = tid & 7;

    const int arow  = (lane < 16) ? lane : (lane - 16);
    const int acol8 = (lane < 16) ? 0 : 8;
    uint32_t aoff[4];
#pragma unroll
    for (int mt = 0; mt < 4; mt++)
        aoff[mt] = (uint32_t)(((wm * 64 + mt * 16 + arow) * SPITCH + acol8) * 2);
    const int bg = lane >> 3;
    uint32_t boff[2];
#pragma unroll
    for (int p = 0; p < 2; p++) {
        int nrow = wn * 32 + (2 * p + (bg >> 1)) * 8 + (lane & 7);
        boff[p] = (uint32_t)((nrow * SPITCH + (bg & 1) * 8) * 2);
    }

    auto load_step = [&](int step, int stage) {
        const int phase = step >> 3;        // 0..4
        const int kk    = (step & 7) * 64;
        const __nv_bfloat16* Ag = (phase < 2) ? g_x1 : (phase < 4 ? g_x2 : g_x3);
        const __nv_bfloat16* Bg = (phase & 1) ? g_w2 : g_w1;
        uint32_t sAb = smem_u32 + stage * 2 * STAGE_BYTES;
        uint32_t sBb = sAb + STAGE_BYTES;
#pragma unroll
        for (int i = 0; i < 4; i++) {
            int r = lrow0 + i * 32;
            size_t goA = (size_t)(m0 + r) * D_DIM + kk + lch * 8;
            size_t goB = (size_t)(n0 + r) * D_DIM + kk + lch * 8;
            cp16(sAb + (uint32_t)((r * SPITCH + lch * 8) * 2), Ag + goA);
            cp16(sBb + (uint32_t)((r * SPITCH + lch * 8) * 2), Bg + goB);
        }
    };

    float acc[4][4][4];
#pragma unroll
    for (int a = 0; a < 4; a++)
#pragma unroll
        for (int b = 0; b < 4; b++)
#pragma unroll
            for (int c = 0; c < 4; c++) acc[a][b][c] = 0.0f;

    load_step(0, 0);
    CP_COMMIT();

    for (int cur = 0; cur < NSTEP1; cur++) {
        // single-sync pipeline: wait own copies of buf cur; barrier publishes
        // them AND orders everyone's compute(cur-1) before overwriting its buf.
        CP_WAIT(0);
        __syncthreads();
        if (cur + 1 < NSTEP1) {
            load_step(cur + 1, (cur + 1) & 1);
            CP_COMMIT();
        }

        const uint32_t sAu = smem_u32 + (uint32_t)((cur & 1) * 2 * STAGE_BYTES);
        const uint32_t sBu = sAu + STAGE_BYTES;
#pragma unroll
        for (int ks = 0; ks < 4; ks++) {
            uint32_t bfr[4][2];
            {
                uint32_t t0[4], t1[4];
                ldsm_x4(t0, sBu + boff[0] + ks * 32);
                ldsm_x4(t1, sBu + boff[1] + ks * 32);
                bfr[0][0] = t0[0]; bfr[0][1] = t0[1];
                bfr[1][0] = t0[2]; bfr[1][1] = t0[3];
                bfr[2][0] = t1[0]; bfr[2][1] = t1[1];
                bfr[3][0] = t1[2]; bfr[3][1] = t1[3];
            }
#pragma unroll
            for (int mt = 0; mt < 4; mt++) {
                uint32_t afr[4];
                ldsm_x4(afr, sAu + aoff[mt] + ks * 32);
#pragma unroll
                for (int nn = 0; nn < 4; nn++)
                    mma16816(acc[mt][nn], afr, bfr[nn]);
            }
        }
    }

    // epilogue: bias + store h (fp32) and hi/lo bf16 splits
    float bia[4][2];
#pragma unroll
    for (int nn = 0; nn < 4; nn++) {
        int col = n0 + wn * 32 + nn * 8 + lr * 2;
        bia[nn][0] = bias[col];
        bia[nn][1] = bias[col + 1];
    }
#pragma unroll
    for (int mt = 0; mt < 4; mt++) {
#pragma unroll
        for (int half = 0; half < 2; half++) {
            const int row = m0 + wm * 64 + mt * 16 + half * 8 + lq;
#pragma unroll
            for (int nn = 0; nn < 4; nn++) {
                const int col = n0 + wn * 32 + nn * 8 + lr * 2;
                float h0 = acc[mt][nn][half * 2 + 0] + bia[nn][0];
                float h1 = acc[mt][nn][half * 2 + 1] + bia[nn][1];
                const size_t o = (size_t)row * D_DIM + col;
                *(float2*)(g_h + o) = make_float2(h0, h1);
                __nv_bfloat16 p0 = __float2bfloat16_rn(h0);
                __nv_bfloat16 p1 = __float2bfloat16_rn(h1);
                __nv_bfloat16 q0 = __float2bfloat16_rn(h0 - __bfloat162float(p0));
                __nv_bfloat16 q1 = __float2bfloat16_rn(h1 - __bfloat162float(p1));
                *(__nv_bfloat162*)(g_hhi + o) = __nv_bfloat162(p0, p1);
                *(__nv_bfloat162*)(g_hlo + o) = __nv_bfloat162(q0, q1);
            }
        }
    }
}

// ---------------------------------------------------------------------------
// prep_emb: ||e_k||^2 (fp32 exact), e -> bf16 hi/lo split, zero counts/nflag
// ---------------------------------------------------------------------------
__global__ void prep_emb_kernel(const float* __restrict__ emb)
{
    __shared__ float red[128];
    const int k   = blockIdx.x;
    const int tid = threadIdx.x;
    const size_t base = (size_t)k * D_DIM + tid * 4;
    float4 v = *(const float4*)(emb + base);
    red[tid] = v.x * v.x + v.y * v.y + v.z * v.z + v.w * v.w;

    __nv_bfloat16 hx = __float2bfloat16_rn(v.x), hy = __float2bfloat16_rn(v.y);
    __nv_bfloat16 hz = __float2bfloat16_rn(v.z), hw = __float2bfloat16_rn(v.w);
    __nv_bfloat16 lx = __float2bfloat16_rn(v.x - __bfloat162float(hx));
    __nv_bfloat16 ly = __float2bfloat16_rn(v.y - __bfloat162float(hy));
    __nv_bfloat16 lz = __float2bfloat16_rn(v.z - __bfloat162float(hz));
    __nv_bfloat16 lw = __float2bfloat16_rn(v.w - __bfloat162float(hw));
    *(__nv_bfloat162*)(g_ehi + base)     = __nv_bfloat162(hx, hy);
    *(__nv_bfloat162*)(g_ehi + base + 2) = __nv_bfloat162(hz, hw);
    *(__nv_bfloat162*)(g_elo + base)     = __nv_bfloat162(lx, ly);
    *(__nv_bfloat162*)(g_elo + base + 2) = __nv_bfloat162(lz, lw);

    __syncthreads();
    for (int off = 64; off; off >>= 1) {
        if (tid < off) red[tid] += red[tid + off];
        __syncthreads();
    }
    if (tid == 0) {
        g_en[k] = red[0];
        g_counts[k] = 0;
        if (k == 0) g_nflag = 0;
    }
}

// ---------------------------------------------------------------------------
// GEMM2: mma.sync bf16 + ldmatrix, virtual K = 1536 (3 phases), single-sync
// 2-stage cp.async pipeline, fused in-register top-2 argmin.
// ---------------------------------------------------------------------------
#define NSTEP 384

__global__ __launch_bounds__(256, 2)
void gemm2_mma_kernel()
{
    extern __shared__ __align__(16) char dsm[];
    const uint32_t smem_u32 = (uint32_t)__cvta_generic_to_shared(dsm);

    const int tid  = threadIdx.x;
    const int lane = tid & 31;
    const int w    = tid >> 5;
    const int wm   = w >> 2;
    const int wn   = w & 3;
    const int lq   = lane >> 2;
    const int lr   = lane & 3;
    const int m0   = blockIdx.x * 128;

    const int lrow0 = tid >> 3;
    const int lch   = tid & 7;

    const int arow  = (lane < 16) ? lane : (lane - 16);
    const int acol8 = (lane < 16) ? 0 : 8;
    uint32_t aoff[4];
#pragma unroll
    for (int mt = 0; mt < 4; mt++)
        aoff[mt] = (uint32_t)(((wm * 64 + mt * 16 + arow) * SPITCH + acol8) * 2);
    const int bg = lane >> 3;
    uint32_t boff[2];
#pragma unroll
    for (int p = 0; p < 2; p++) {
        int nrow = wn * 32 + (2 * p + (bg >> 1)) * 8 + (lane & 7);
        boff[p] = (uint32_t)((nrow * SPITCH + (bg & 1) * 8) * 2);
    }

    float v1[8], v2[8]; int i1[8];
#pragma unroll
    for (int s = 0; s < 8; s++) { v1[s] = 3.4e38f; v2[s] = 3.4e38f; i1[s] = 0; }

#define UPD(sl, cc, ss) do { float _s = (ss); \
    if (_s < v1[sl]) { v2[sl] = v1[sl]; v1[sl] = _s; i1[sl] = (cc); } \
    else if (_s < v2[sl]) v2[sl] = _s; } while (0)

    auto load_step = [&](int step, int stage) {
        const int nt    = step / 24;
        const int vc    = step - nt * 24;
        const int phase = vc >> 3;
        const int kk    = (vc & 7) * 64;
        const int n0    = nt * 128;
        const __nv_bfloat16* Ag = (phase < 2)  ? g_hhi : g_hlo;
        const __nv_bfloat16* Bg = (phase == 1) ? g_elo : g_ehi;
        uint32_t sAb = smem_u32 + stage * 2 * STAGE_BYTES;
        uint32_t sBb = sAb + STAGE_BYTES;
#pragma unroll
        for (int i = 0; i < 4; i++) {
            int r = lrow0 + i * 32;
            size_t goA = (size_t)(m0 + r) * D_DIM + kk + lch * 8;
            size_t goB = (size_t)(n0 + r) * D_DIM + kk + lch * 8;
            cp16(sAb + (uint32_t)((r * SPITCH + lch * 8) * 2), Ag + goA);
            cp16(sBb + (uint32_t)((r * SPITCH + lch * 8) * 2), Bg + goB);
        }
    };

    load_step(0, 0);
    CP_COMMIT();

    float acc[4][4][4];
    for (int nt = 0; nt < 16; nt++) {
        const int n0 = nt * 128;
#pragma unroll
        for (int a = 0; a < 4; a++)
#pragma unroll
            for (int b = 0; b < 4; b++)
#pragma unroll
                for (int c = 0; c < 4; c++) acc[a][b][c] = 0.0f;

        for (int vc = 0; vc < 24; vc++) {
            const int cur = nt * 24 + vc;
            CP_WAIT(0);
            __syncthreads();
            if (cur + 1 < NSTEP) {
                load_step(cur + 1, (cur + 1) & 1);
                CP_COMMIT();
            }

            const uint32_t sAu = smem_u32 + (uint32_t)((cur & 1) * 2 * STAGE_BYTES);
            const uint32_t sBu = sAu + STAGE_BYTES;
#pragma unroll
            for (int ks = 0; ks < 4; ks++) {
                uint32_t bfr[4][2];
                {
                    uint32_t t0[4], t1[4];
                    ldsm_x4(t0, sBu + boff[0] + ks * 32);
                    ldsm_x4(t1, sBu + boff[1] + ks * 32);
                    bfr[0][0] = t0[0]; bfr[0][1] = t0[1];
                    bfr[1][0] = t0[2]; bfr[1][1] = t0[3];
                    bfr[2][0] = t1[0]; bfr[2][1] = t1[1];
                    bfr[3][0] = t1[2]; bfr[3][1] = t1[3];
                }
#pragma unroll
                for (int mt = 0; mt < 4; mt++) {
                    uint32_t afr[4];
                    ldsm_x4(afr, sAu + aoff[mt] + ks * 32);
#pragma unroll
                    for (int nn = 0; nn < 4; nn++)
                        mma16816(acc[mt][nn], afr, bfr[nn]);
                }
            }
        }

#pragma unroll
        for (int mt = 0; mt < 4; mt++) {
#pragma unroll
            for (int nn = 0; nn < 4; nn++) {
                const int col = n0 + wn * 32 + nn * 8 + lr * 2;
                const float e0 = g_en[col], e1 = g_en[col + 1];
                const int s0 = mt * 2, s1 = mt * 2 + 1;
                UPD(s0, col,     e0 - 2.0f * acc[mt][nn][0]);
                UPD(s0, col + 1, e1 - 2.0f * acc[mt][nn][1]);
                UPD(s1, col,     e0 - 2.0f * acc[mt][nn][2]);
                UPD(s1, col + 1, e1 - 2.0f * acc[mt][nn][3]);
            }
        }
    }

#pragma unroll
    for (int off = 1; off <= 2; off <<= 1) {
#pragma unroll
        for (int sl = 0; sl < 8; sl++) {
            float ov1 = __shfl_xor_sync(0xffffffffu, v1[sl], off);
            int   oi1 = __shfl_xor_sync(0xffffffffu, i1[sl], off);
            float ov2 = __shfl_xor_sync(0xffffffffu, v2[sl], off);
            if (ov1 < v1[sl] || (ov1 == v1[sl] && oi1 < i1[sl])) {
                v2[sl] = fminf(v1[sl], ov2); v1[sl] = ov1; i1[sl] = oi1;
            } else {
                v2[sl] = fminf(v2[sl], ov1);
            }
        }
    }

    __syncthreads();
    float* rv1 = (float*)dsm;
    int*   ri1 = (int*)(dsm + 2048);
    float* rv2 = (float*)(dsm + 4096);
    if (lr == 0) {
#pragma unroll
        for (int sl = 0; sl < 8; sl++) {
            int row = wm * 64 + (sl >> 1) * 16 + (sl & 1) * 8 + lq;
            rv1[row * 4 + wn] = v1[sl];
            ri1[row * 4 + wn] = i1[sl];
            rv2[row * 4 + wn] = v2[sl];
        }
    }
    __syncthreads();
    if (tid < 128) {
        float bv1 = rv1[tid * 4]; int bi1 = ri1[tid * 4]; float bv2 = rv2[tid * 4];
#pragma unroll
        for (int j = 1; j < 4; j++) {
            float ov1 = rv1[tid * 4 + j]; int oi1 = ri1[tid * 4 + j]; float ov2 = rv2[tid * 4 + j];
            if (ov1 < bv1 || (ov1 == bv1 && oi1 < bi1)) {
                bv2 = fminf(bv1, ov2); bv1 = ov1; bi1 = oi1;
            } else {
                bv2 = fminf(bv2, ov1);
            }
        }
        const int row = m0 + tid;
        if (bv2 - bv1 <= MARGIN) {
            g_idx[row]  = -1;
            g_best[row] = 0xFFFFFFFFFFFFFFFFull;
            int slot = atomicAdd(&g_nflag, 1);
            g_flagged[slot] = row;
        } else {
            g_idx[row] = bi1;
        }
    }
}

// ---------------------------------------------------------------------------
// Fallback: exact fp32 argmin for flagged rows; packed atomicMin combine.
// ---------------------------------------------------------------------------
__global__ __launch_bounds__(256)
void fallback_kernel(const float* __restrict__ emb)
{
    __shared__ float hrow[D_DIM];
    const int tid = threadIdx.x;
    const int cnt = g_nflag;
    const int total = cnt * 8;

    for (int wk = blockIdx.x; wk < total; wk += gridDim.x) {
        const int f     = wk >> 3;
        const int chunk = wk & 7;
        const int row   = g_flagged[f];

        if (tid < 128)
            *(float4*)(hrow + tid * 4) = *(const float4*)(g_h + (size_t)row * D_DIM + tid * 4);
        __syncthreads();

        const int k = chunk * 256 + tid;
        const float4* ep = (const float4*)(emb + (size_t)k * D_DIM);
        float a0 = 0.f, a1 = 0.f, a2 = 0.f, a3 = 0.f;
#pragma unroll 16
        for (int d4 = 0; d4 < D_DIM / 4; d4++) {
            float4 e = ep[d4];
            float4 h = *(const float4*)(hrow + d4 * 4);
            a0 += e.x * h.x; a1 += e.y * h.y; a2 += e.z * h.z; a3 += e.w * h.w;
        }
        float s = g_en[k] - 2.0f * ((a0 + a1) + (a2 + a3));
        unsigned long long key = ((unsigned long long)fmap(s) << 32) | (unsigned)k;
        atomicMin(&g_best[row], key);
        __syncthreads();
    }
}

// ---------------------------------------------------------------------------
// Epilogue per row: q_out, encodings (float2 — OFF_ENC is 8B-aligned only),
// loss partial, counts
// ---------------------------------------------------------------------------
__global__ void epilogue_kernel(const float* __restrict__ emb, float* __restrict__ out)
{
    __shared__ float red[128];
    const int n   = blockIdx.x;
    const int tid = threadIdx.x;
    int idx = g_idx[n];
    if (idx < 0) idx = (int)(g_best[n] & 0xFFFFFFFFull);

    float4 hv = *(const float4*)(g_h + (size_t)n * D_DIM + tid * 4);
    float4 qv = *(const float4*)(emb + (size_t)idx * D_DIM + tid * 4);
    float d0 = qv.x - hv.x, d1 = qv.y - hv.y, d2 = qv.z - hv.z, d3 = qv.w - hv.w;

    float* qo = out + OFF_QOUT + (size_t)n * D_DIM + tid * 4;
    qo[0] = hv.x + d0; qo[1] = hv.y + d1; qo[2] = hv.z + d2; qo[3] = hv.w + d3;

    red[tid] = d0 * d0 + d1 * d1 + d2 * d2 + d3 * d3;

    float2* er2 = (float2*)(out + OFF_ENC + (size_t)n * K_CODES);
    const int unit = idx >> 1, comp = idx & 1;
#pragma unroll
    for (int i = 0; i < 8; i++) {
        int u = tid + i * 128;
        float2 v = make_float2(0.0f, 0.0f);
        if (u == unit) { if (comp == 0) v.x = 1.0f; else v.y = 1.0f; }
        er2[u] = v;
    }

    __syncthreads();
    for (int off = 64; off; off >>= 1) {
        if (tid < off) red[tid] += red[tid + off];
        __syncthreads();
    }
    if (tid == 0) {
        g_partial[n] = red[0];
        atomicAdd(&g_counts[idx], 1);
    }
}

// ---------------------------------------------------------------------------
__global__ void final_kernel(float* __restrict__ out)
{
    __shared__ float red[1024];
    const int tid = threadIdx.x;

    float s = 0.0f;
    for (int i = 0; i < N_ROWS / 1024; i++) s += g_partial[tid + i * 1024];
    red[tid] = s;
    __syncthreads();
    for (int off = 512; off; off >>= 1) {
        if (tid < off) red[tid] += red[tid + off];
        __syncthreads();
    }
    if (tid == 0) out[0] = 0.25f * red[0] / (float)((size_t)N_ROWS * D_DIM);
    __syncthreads();

    float p = 0.0f;
    for (int i = 0; i < K_CODES / 1024; i++) {
        float c  = (float)g_counts[tid + i * 1024];
        float pr = c * (1.0f / (float)N_ROWS);
        p += pr * logf(pr + 1e-10f);
    }
    red[tid] = p;
    __syncthreads();
    for (int off = 512; off; off >>= 1) {
        if (tid < off) red[tid] += red[tid + off];
        __syncthreads();
    }
    if (tid == 0) out[OFF_PERP] = expf(-red[0]);
}

// ---------------------------------------------------------------------------
extern "C" void kernel_launch(void* const* d_in, const int* in_sizes, int n_in,
                              void* d_out, int out_size)
{
    const float *x0 = nullptr, *x1 = nullptr, *W = nullptr, *b = nullptr, *emb = nullptr;
    for (int i = 0; i < n_in; i++) {
        const float* p = (const float*)d_in[i];
        const long long s = in_sizes[i];
        if (s == (long long)N_ROWS * HALFW)       { if (!x0) x0 = p; else x1 = p; }
        else if (s == (long long)D_DIM * D_DIM)   W = p;
        else if (s == (long long)D_DIM)           b = p;
        else if (s == (long long)K_CODES * D_DIM) emb = p;
    }
    float* out = (float*)d_out;

    static int smem_set = 0;
    if (!smem_set) {
        cudaFuncSetAttribute(gemm2_mma_kernel,
                             cudaFuncAttributeMaxDynamicSharedMemorySize, 4 * STAGE_BYTES);
        cudaFuncSetAttribute(gemm1_mma_kernel,
                             cudaFuncAttributeMaxDynamicSharedMemorySize, 4 * STAGE_BYTES);
        smem_set = 1;
    }

    prep_x_kernel<<<(N_ROWS * D_DIM) / 1024, 256>>>(x0, x1);
    prep_w_kernel<<<(D_DIM * D_DIM) / 1024, 256>>>(W);
    prep_emb_kernel<<<K_CODES, 128>>>(emb);
    gemm1_mma_kernel<<<dim3(D_DIM / 128, N_ROWS / 128), 256, 4 * STAGE_BYTES>>>(b);
    gemm2_mma_kernel<<<N_ROWS / 128, 256, 4 * STAGE_BYTES>>>();
    fallback_kernel<<<2048, 256>>>(emb);
    epilogue_kernel<<<N_ROWS, 128>>>(emb, out);
    final_kernel<<<1, 1024>>>(out);
}

// round 9
// speedup vs baseline: 3.9078x; 1.7385x over previous
#include <cuda_runtime.h>
#include <cuda_bf16.h>
#include <math.h>
#include <stdint.h>

// Problem constants
#define N_ROWS  32768
#define D_DIM   512
#define K_CODES 2048
#define HALFW   256

// Output layout: [loss(1) | q_out(2*32768*256) | perplexity(1) | encodings(32768*2048)]
#define OFF_QOUT 1
#define OFF_PERP (1 + N_ROWS * D_DIM)
#define OFF_ENC  (2 + N_ROWS * D_DIM)   // 8-byte aligned only

#define MARGIN1 0.30f   // pass-1 (bf16 single-phase) flag margin
#define MARGIN2 0.02f   // pass-2 (3-phase split) exact-fallback margin
#define MAXF    8192

// Scratch (device globals: allocation-free per harness rules)
__device__ float         g_h[(size_t)N_ROWS * D_DIM];
__device__ __nv_bfloat16 g_hhi[(size_t)N_ROWS * D_DIM];
__device__ __nv_bfloat16 g_hlo[(size_t)N_ROWS * D_DIM];
__device__ __nv_bfloat16 g_ehi[(size_t)K_CODES * D_DIM];
__device__ __nv_bfloat16 g_elo[(size_t)K_CODES * D_DIM];
__device__ __nv_bfloat16 g_x1[(size_t)N_ROWS * D_DIM];
__device__ __nv_bfloat16 g_x2[(size_t)N_ROWS * D_DIM];
__device__ __nv_bfloat16 g_w1[(size_t)D_DIM * D_DIM];
__device__ __nv_bfloat16 g_w2[(size_t)D_DIM * D_DIM];
__device__ __nv_bfloat16 g_fhi[(size_t)MAXF * D_DIM];
__device__ __nv_bfloat16 g_flo[(size_t)MAXF * D_DIM];
__device__ unsigned long long g_p2k[(size_t)MAXF * 16];
__device__ float g_p2v[(size_t)MAXF * 16];
__device__ float g_en[K_CODES];
__device__ int   g_idx[N_ROWS];
__device__ float g_partial[N_ROWS];
__device__ int   g_counts[K_CODES];
__device__ int   g_nflag;               // exact-fallback list
__device__ int   g_flagged[N_ROWS];
__device__ int   g_nflag1;              // pass-1 list
__device__ int   g_flag1[N_ROWS];
__device__ unsigned long long g_best[N_ROWS];

// ---------------------------------------------------------------------------
// PTX helpers
// ---------------------------------------------------------------------------
__device__ __forceinline__ void mma16816(float* c, const uint32_t* a, const uint32_t* b) {
    asm volatile(
        "mma.sync.aligned.m16n8k16.row.col.f32.bf16.bf16.f32 "
        "{%0,%1,%2,%3}, {%4,%5,%6,%7}, {%8,%9}, {%0,%1,%2,%3};"
        : "+f"(c[0]), "+f"(c[1]), "+f"(c[2]), "+f"(c[3])
        : "r"(a[0]), "r"(a[1]), "r"(a[2]), "r"(a[3]), "r"(b[0]), "r"(b[1]));
}
__device__ __forceinline__ void ldsm_x4(uint32_t* r, uint32_t addr) {
    asm volatile("ldmatrix.sync.aligned.m8n8.x4.shared.b16 {%0,%1,%2,%3}, [%4];"
                 : "=r"(r[0]), "=r"(r[1]), "=r"(r[2]), "=r"(r[3]) : "r"(addr));
}
__device__ __forceinline__ void cp16(uint32_t dst_smem, const void* src) {
    asm volatile("cp.async.cg.shared.global [%0], [%1], 16;" :: "r"(dst_smem), "l"(src));
}
#define CP_COMMIT() asm volatile("cp.async.commit_group;" ::: "memory")
#define CP_WAIT(N)  asm volatile("cp.async.wait_group %0;" :: "n"(N) : "memory")

__device__ __forceinline__ uint32_t fmap(float f) {  // order-preserving float->uint
    uint32_t u = __float_as_uint(f);
    return (u & 0x80000000u) ? ~u : (u | 0x80000000u);
}
__device__ __forceinline__ float funmap(uint32_t m) {
    return (m & 0x80000000u) ? __uint_as_float(m ^ 0x80000000u) : __uint_as_float(~m);
}

#define SPITCH 72
#define STAGE_BYTES (128 * SPITCH * 2)

// ---------------------------------------------------------------------------
// prep_x: concat(x0,x1) -> 2-way bf16 split
// ---------------------------------------------------------------------------
__global__ void prep_x_kernel(const float* __restrict__ x0, const float* __restrict__ x1)
{
    const size_t i = ((size_t)blockIdx.x * 256 + threadIdx.x) * 4;
    const int col = (int)(i & (D_DIM - 1));
    const size_t row = i >> 9;
    const float* src = (col < HALFW) ? (x0 + row * HALFW + col)
                                     : (x1 + row * HALFW + (col - HALFW));
    float4 v = *(const float4*)src;
    float e[4] = {v.x, v.y, v.z, v.w};
    __nv_bfloat16 a[4], b[4];
#pragma unroll
    for (int j = 0; j < 4; j++) {
        a[j] = __float2bfloat16_rn(e[j]);
        b[j] = __float2bfloat16_rn(e[j] - __bfloat162float(a[j]));
    }
    *(__nv_bfloat162*)(g_x1 + i)     = __nv_bfloat162(a[0], a[1]);
    *(__nv_bfloat162*)(g_x1 + i + 2) = __nv_bfloat162(a[2], a[3]);
    *(__nv_bfloat162*)(g_x2 + i)     = __nv_bfloat162(b[0], b[1]);
    *(__nv_bfloat162*)(g_x2 + i + 2) = __nv_bfloat162(b[2], b[3]);
}

// prep_w: W -> 2-way bf16 split
__global__ void prep_w_kernel(const float* __restrict__ W)
{
    const size_t i = ((size_t)blockIdx.x * 256 + threadIdx.x) * 4;
    float4 v = *(const float4*)(W + i);
    float e[4] = {v.x, v.y, v.z, v.w};
    __nv_bfloat16 a[4], b[4];
#pragma unroll
    for (int j = 0; j < 4; j++) {
        a[j] = __float2bfloat16_rn(e[j]);
        b[j] = __float2bfloat16_rn(e[j] - __bfloat162float(a[j]));
    }
    *(__nv_bfloat162*)(g_w1 + i)     = __nv_bfloat162(a[0], a[1]);
    *(__nv_bfloat162*)(g_w1 + i + 2) = __nv_bfloat162(a[2], a[3]);
    *(__nv_bfloat162*)(g_w2 + i)     = __nv_bfloat162(b[0], b[1]);
    *(__nv_bfloat162*)(g_w2 + i + 2) = __nv_bfloat162(b[2], b[3]);
}

// ---------------------------------------------------------------------------
// GEMM1 via mma.sync bf16, 3-phase: X1W1, X1W2, X2W1.
// ---------------------------------------------------------------------------
#define NSTEP1 24

__global__ __launch_bounds__(256, 2)
void gemm1_mma_kernel(const float* __restrict__ bias)
{
    extern __shared__ __align__(16) char dsm[];
    const uint32_t smem_u32 = (uint32_t)__cvta_generic_to_shared(dsm);

    const int tid  = threadIdx.x;
    const int lane = tid & 31;
    const int w    = tid >> 5;
    const int wm   = w >> 2;
    const int wn   = w & 3;
    const int lq   = lane >> 2;
    const int lr   = lane & 3;
    const int m0   = blockIdx.y * 128;
    const int n0   = blockIdx.x * 128;

    const int lrow0 = tid >> 3;
    const int lch   = tid & 7;

    const int arow  = (lane < 16) ? lane : (lane - 16);
    const int acol8 = (lane < 16) ? 0 : 8;
    uint32_t aoff[4];
#pragma unroll
    for (int mt = 0; mt < 4; mt++)
        aoff[mt] = (uint32_t)(((wm * 64 + mt * 16 + arow) * SPITCH + acol8) * 2);
    const int bg = lane >> 3;
    uint32_t boff[2];
#pragma unroll
    for (int p = 0; p < 2; p++) {
        int nrow = wn * 32 + (2 * p + (bg >> 1)) * 8 + (lane & 7);
        boff[p] = (uint32_t)((nrow * SPITCH + (bg & 1) * 8) * 2);
    }

    auto load_step = [&](int step, int stage) {
        const int phase = step >> 3;        // 0..2
        const int kk    = (step & 7) * 64;
        const __nv_bfloat16* Ag = (phase < 2) ? g_x1 : g_x2;
        const __nv_bfloat16* Bg = (phase == 1) ? g_w2 : g_w1;
        uint32_t sAb = smem_u32 + stage * 2 * STAGE_BYTES;
        uint32_t sBb = sAb + STAGE_BYTES;
#pragma unroll
        for (int i = 0; i < 4; i++) {
            int r = lrow0 + i * 32;
            cp16(sAb + (uint32_t)((r * SPITCH + lch * 8) * 2),
                 Ag + (size_t)(m0 + r) * D_DIM + kk + lch * 8);
            cp16(sBb + (uint32_t)((r * SPITCH + lch * 8) * 2),
                 Bg + (size_t)(n0 + r) * D_DIM + kk + lch * 8);
        }
    };

    float acc[4][4][4];
#pragma unroll
    for (int a = 0; a < 4; a++)
#pragma unroll
        for (int b = 0; b < 4; b++)
#pragma unroll
            for (int c = 0; c < 4; c++) acc[a][b][c] = 0.0f;

    load_step(0, 0);
    CP_COMMIT();

    for (int cur = 0; cur < NSTEP1; cur++) {
        CP_WAIT(0);
        __syncthreads();
        if (cur + 1 < NSTEP1) {
            load_step(cur + 1, (cur + 1) & 1);
            CP_COMMIT();
        }
        const uint32_t sAu = smem_u32 + (uint32_t)((cur & 1) * 2 * STAGE_BYTES);
        const uint32_t sBu = sAu + STAGE_BYTES;
#pragma unroll
        for (int ks = 0; ks < 4; ks++) {
            uint32_t bfr[4][2];
            {
                uint32_t t0[4], t1[4];
                ldsm_x4(t0, sBu + boff[0] + ks * 32);
                ldsm_x4(t1, sBu + boff[1] + ks * 32);
                bfr[0][0] = t0[0]; bfr[0][1] = t0[1];
                bfr[1][0] = t0[2]; bfr[1][1] = t0[3];
                bfr[2][0] = t1[0]; bfr[2][1] = t1[1];
                bfr[3][0] = t1[2]; bfr[3][1] = t1[3];
            }
#pragma unroll
            for (int mt = 0; mt < 4; mt++) {
                uint32_t afr[4];
                ldsm_x4(afr, sAu + aoff[mt] + ks * 32);
#pragma unroll
                for (int nn = 0; nn < 4; nn++)
                    mma16816(acc[mt][nn], afr, bfr[nn]);
            }
        }
    }

    float bia[4][2];
#pragma unroll
    for (int nn = 0; nn < 4; nn++) {
        int col = n0 + wn * 32 + nn * 8 + lr * 2;
        bia[nn][0] = bias[col];
        bia[nn][1] = bias[col + 1];
    }
#pragma unroll
    for (int mt = 0; mt < 4; mt++) {
#pragma unroll
        for (int half = 0; half < 2; half++) {
            const int row = m0 + wm * 64 + mt * 16 + half * 8 + lq;
#pragma unroll
            for (int nn = 0; nn < 4; nn++) {
                const int col = n0 + wn * 32 + nn * 8 + lr * 2;
                float h0 = acc[mt][nn][half * 2 + 0] + bia[nn][0];
                float h1 = acc[mt][nn][half * 2 + 1] + bia[nn][1];
                const size_t o = (size_t)row * D_DIM + col;
                *(float2*)(g_h + o) = make_float2(h0, h1);
                __nv_bfloat16 p0 = __float2bfloat16_rn(h0);
                __nv_bfloat16 p1 = __float2bfloat16_rn(h1);
                __nv_bfloat16 q0 = __float2bfloat16_rn(h0 - __bfloat162float(p0));
                __nv_bfloat16 q1 = __float2bfloat16_rn(h1 - __bfloat162float(p1));
                *(__nv_bfloat162*)(g_hhi + o) = __nv_bfloat162(p0, p1);
                *(__nv_bfloat162*)(g_hlo + o) = __nv_bfloat162(q0, q1);
            }
        }
    }
}

// ---------------------------------------------------------------------------
// prep_emb
// ---------------------------------------------------------------------------
__global__ void prep_emb_kernel(const float* __restrict__ emb)
{
    __shared__ float red[128];
    const int k   = blockIdx.x;
    const int tid = threadIdx.x;
    const size_t base = (size_t)k * D_DIM + tid * 4;
    float4 v = *(const float4*)(emb + base);
    red[tid] = v.x * v.x + v.y * v.y + v.z * v.z + v.w * v.w;

    __nv_bfloat16 hx = __float2bfloat16_rn(v.x), hy = __float2bfloat16_rn(v.y);
    __nv_bfloat16 hz = __float2bfloat16_rn(v.z), hw = __float2bfloat16_rn(v.w);
    __nv_bfloat16 lx = __float2bfloat16_rn(v.x - __bfloat162float(hx));
    __nv_bfloat16 ly = __float2bfloat16_rn(v.y - __bfloat162float(hy));
    __nv_bfloat16 lz = __float2bfloat16_rn(v.z - __bfloat162float(hz));
    __nv_bfloat16 lw = __float2bfloat16_rn(v.w - __bfloat162float(hw));
    *(__nv_bfloat162*)(g_ehi + base)     = __nv_bfloat162(hx, hy);
    *(__nv_bfloat162*)(g_ehi + base + 2) = __nv_bfloat162(hz, hw);
    *(__nv_bfloat162*)(g_elo + base)     = __nv_bfloat162(lx, ly);
    *(__nv_bfloat162*)(g_elo + base + 2) = __nv_bfloat162(lz, lw);

    __syncthreads();
    for (int off = 64; off; off >>= 1) {
        if (tid < off) red[tid] += red[tid + off];
        __syncthreads();
    }
    if (tid == 0) {
        g_en[k] = red[0];
        g_counts[k] = 0;
        if (k == 0) { g_nflag = 0; g_nflag1 = 0; }
    }
}

// ---------------------------------------------------------------------------
// GEMM2 pass 1: SINGLE-phase bf16 (hhi.ehi), K=512, top-2 + wide margin flag.
// ---------------------------------------------------------------------------
#define NSTEP_P1 128   // 16 nt * 8 chunks

__global__ __launch_bounds__(256, 2)
void gemm2_pass1_kernel()
{
    extern __shared__ __align__(16) char dsm[];
    const uint32_t smem_u32 = (uint32_t)__cvta_generic_to_shared(dsm);

    const int tid  = threadIdx.x;
    const int lane = tid & 31;
    const int w    = tid >> 5;
    const int wm   = w >> 2;
    const int wn   = w & 3;
    const int lq   = lane >> 2;
    const int lr   = lane & 3;
    const int m0   = blockIdx.x * 128;

    const int lrow0 = tid >> 3;
    const int lch   = tid & 7;

    const int arow  = (lane < 16) ? lane : (lane - 16);
    const int acol8 = (lane < 16) ? 0 : 8;
    uint32_t aoff[4];
#pragma unroll
    for (int mt = 0; mt < 4; mt++)
        aoff[mt] = (uint32_t)(((wm * 64 + mt * 16 + arow) * SPITCH + acol8) * 2);
    const int bg = lane >> 3;
    uint32_t boff[2];
#pragma unroll
    for (int p = 0; p < 2; p++) {
        int nrow = wn * 32 + (2 * p + (bg >> 1)) * 8 + (lane & 7);
        boff[p] = (uint32_t)((nrow * SPITCH + (bg & 1) * 8) * 2);
    }

    float v1[8], v2[8]; int i1[8];
#pragma unroll
    for (int s = 0; s < 8; s++) { v1[s] = 3.4e38f; v2[s] = 3.4e38f; i1[s] = 0; }

#define UPD(sl, cc, ss) do { float _s = (ss); \
    if (_s < v1[sl]) { v2[sl] = v1[sl]; v1[sl] = _s; i1[sl] = (cc); } \
    else if (_s < v2[sl]) v2[sl] = _s; } while (0)

    auto load_step = [&](int step, int stage) {
        const int nt = step >> 3;
        const int kk = (step & 7) * 64;
        const int n0 = nt * 128;
        uint32_t sAb = smem_u32 + stage * 2 * STAGE_BYTES;
        uint32_t sBb = sAb + STAGE_BYTES;
#pragma unroll
        for (int i = 0; i < 4; i++) {
            int r = lrow0 + i * 32;
            cp16(sAb + (uint32_t)((r * SPITCH + lch * 8) * 2),
                 g_hhi + (size_t)(m0 + r) * D_DIM + kk + lch * 8);
            cp16(sBb + (uint32_t)((r * SPITCH + lch * 8) * 2),
                 g_ehi + (size_t)(n0 + r) * D_DIM + kk + lch * 8);
        }
    };

    load_step(0, 0);
    CP_COMMIT();

    float acc[4][4][4];
    for (int nt = 0; nt < 16; nt++) {
        const int n0 = nt * 128;
#pragma unroll
        for (int a = 0; a < 4; a++)
#pragma unroll
            for (int b = 0; b < 4; b++)
#pragma unroll
                for (int c = 0; c < 4; c++) acc[a][b][c] = 0.0f;

        for (int vc = 0; vc < 8; vc++) {
            const int cur = nt * 8 + vc;
            CP_WAIT(0);
            __syncthreads();
            if (cur + 1 < NSTEP_P1) {
                load_step(cur + 1, (cur + 1) & 1);
                CP_COMMIT();
            }
            const uint32_t sAu = smem_u32 + (uint32_t)((cur & 1) * 2 * STAGE_BYTES);
            const uint32_t sBu = sAu + STAGE_BYTES;
#pragma unroll
            for (int ks = 0; ks < 4; ks++) {
                uint32_t bfr[4][2];
                {
                    uint32_t t0[4], t1[4];
                    ldsm_x4(t0, sBu + boff[0] + ks * 32);
                    ldsm_x4(t1, sBu + boff[1] + ks * 32);
                    bfr[0][0] = t0[0]; bfr[0][1] = t0[1];
                    bfr[1][0] = t0[2]; bfr[1][1] = t0[3];
                    bfr[2][0] = t1[0]; bfr[2][1] = t1[1];
                    bfr[3][0] = t1[2]; bfr[3][1] = t1[3];
                }
#pragma unroll
                for (int mt = 0; mt < 4; mt++) {
                    uint32_t afr[4];
                    ldsm_x4(afr, sAu + aoff[mt] + ks * 32);
#pragma unroll
                    for (int nn = 0; nn < 4; nn++)
                        mma16816(acc[mt][nn], afr, bfr[nn]);
                }
            }
        }

#pragma unroll
        for (int mt = 0; mt < 4; mt++) {
#pragma unroll
            for (int nn = 0; nn < 4; nn++) {
                const int col = n0 + wn * 32 + nn * 8 + lr * 2;
                const float e0 = g_en[col], e1 = g_en[col + 1];
                const int s0 = mt * 2, s1 = mt * 2 + 1;
                UPD(s0, col,     e0 - 2.0f * acc[mt][nn][0]);
                UPD(s0, col + 1, e1 - 2.0f * acc[mt][nn][1]);
                UPD(s1, col,     e0 - 2.0f * acc[mt][nn][2]);
                UPD(s1, col + 1, e1 - 2.0f * acc[mt][nn][3]);
            }
        }
    }

#pragma unroll
    for (int off = 1; off <= 2; off <<= 1) {
#pragma unroll
        for (int sl = 0; sl < 8; sl++) {
            float ov1 = __shfl_xor_sync(0xffffffffu, v1[sl], off);
            int   oi1 = __shfl_xor_sync(0xffffffffu, i1[sl], off);
            float ov2 = __shfl_xor_sync(0xffffffffu, v2[sl], off);
            if (ov1 < v1[sl] || (ov1 == v1[sl] && oi1 < i1[sl])) {
                v2[sl] = fminf(v1[sl], ov2); v1[sl] = ov1; i1[sl] = oi1;
            } else {
                v2[sl] = fminf(v2[sl], ov1);
            }
        }
    }

    __syncthreads();
    float* rv1 = (float*)dsm;
    int*   ri1 = (int*)(dsm + 2048);
    float* rv2 = (float*)(dsm + 4096);
    if (lr == 0) {
#pragma unroll
        for (int sl = 0; sl < 8; sl++) {
            int row = wm * 64 + (sl >> 1) * 16 + (sl & 1) * 8 + lq;
            rv1[row * 4 + wn] = v1[sl];
            ri1[row * 4 + wn] = i1[sl];
            rv2[row * 4 + wn] = v2[sl];
        }
    }
    __syncthreads();
    if (tid < 128) {
        float bv1 = rv1[tid * 4]; int bi1 = ri1[tid * 4]; float bv2 = rv2[tid * 4];
#pragma unroll
        for (int j = 1; j < 4; j++) {
            float ov1 = rv1[tid * 4 + j]; int oi1 = ri1[tid * 4 + j]; float ov2 = rv2[tid * 4 + j];
            if (ov1 < bv1 || (ov1 == bv1 && oi1 < bi1)) {
                bv2 = fminf(bv1, ov2); bv1 = ov1; bi1 = oi1;
            } else {
                bv2 = fminf(bv2, ov1);
            }
        }
        const int row = m0 + tid;
        g_idx[row] = bi1;   // provisional; flagged rows resolved later
        if (bv2 - bv1 <= MARGIN1) {
            int slot = atomicAdd(&g_nflag1, 1);
            if (slot < MAXF) g_flag1[slot] = row;
        }
    }
}

// ---------------------------------------------------------------------------
// gather flagged rows' hhi/hlo into compact buffers
// ---------------------------------------------------------------------------
__global__ __launch_bounds__(128)
void gather_kernel()
{
    const int cnt = min(g_nflag1, MAXF);
    const int tid = threadIdx.x;
    for (int f = blockIdx.x; f < cnt; f += gridDim.x) {
        const int row = g_flag1[f];
        const uint32_t* shi = (const uint32_t*)(g_hhi + (size_t)row * D_DIM);
        const uint32_t* slo = (const uint32_t*)(g_hlo + (size_t)row * D_DIM);
        uint32_t* dhi = (uint32_t*)(g_fhi + (size_t)f * D_DIM);
        uint32_t* dlo = (uint32_t*)(g_flo + (size_t)f * D_DIM);
        dhi[tid * 2] = shi[tid * 2]; dhi[tid * 2 + 1] = shi[tid * 2 + 1];
        dlo[tid * 2] = slo[tid * 2]; dlo[tid * 2 + 1] = slo[tid * 2 + 1];
    }
}

// ---------------------------------------------------------------------------
// pass 2: 3-phase split scores for flagged rows. Grid = 64 rowtiles x 16 nt;
// each CTA: 128 compact rows x 128 codes, local top-2 -> g_p2k/g_p2v.
// ---------------------------------------------------------------------------
__global__ __launch_bounds__(256, 2)
void gemm2_pass2_kernel()
{
    const int cnt = min(g_nflag1, MAXF);
    const int rt = blockIdx.x >> 4;
    const int nt = blockIdx.x & 15;
    if (rt * 128 >= cnt) return;

    extern __shared__ __align__(16) char dsm[];
    const uint32_t smem_u32 = (uint32_t)__cvta_generic_to_shared(dsm);

    const int tid  = threadIdx.x;
    const int lane = tid & 31;
    const int w    = tid >> 5;
    const int wm   = w >> 2;
    const int wn   = w & 3;
    const int lq   = lane >> 2;
    const int lr   = lane & 3;
    const int f0   = rt * 128;
    const int n0   = nt * 128;

    const int lrow0 = tid >> 3;
    const int lch   = tid & 7;

    const int arow  = (lane < 16) ? lane : (lane - 16);
    const int acol8 = (lane < 16) ? 0 : 8;
    uint32_t aoff[4];
#pragma unroll
    for (int mt = 0; mt < 4; mt++)
        aoff[mt] = (uint32_t)(((wm * 64 + mt * 16 + arow) * SPITCH + acol8) * 2);
    const int bg = lane >> 3;
    uint32_t boff[2];
#pragma unroll
    for (int p = 0; p < 2; p++) {
        int nrow = wn * 32 + (2 * p + (bg >> 1)) * 8 + (lane & 7);
        boff[p] = (uint32_t)((nrow * SPITCH + (bg & 1) * 8) * 2);
    }

    auto load_step = [&](int step, int stage) {
        const int phase = step >> 3;        // 0: fhi*ehi, 1: fhi*elo, 2: flo*ehi
        const int kk    = (step & 7) * 64;
        const __nv_bfloat16* Ag = (phase < 2)  ? g_fhi : g_flo;
        const __nv_bfloat16* Bg = (phase == 1) ? g_elo : g_ehi;
        uint32_t sAb = smem_u32 + stage * 2 * STAGE_BYTES;
        uint32_t sBb = sAb + STAGE_BYTES;
#pragma unroll
        for (int i = 0; i < 4; i++) {
            int r = lrow0 + i * 32;
            cp16(sAb + (uint32_t)((r * SPITCH + lch * 8) * 2),
                 Ag + (size_t)(f0 + r) * D_DIM + kk + lch * 8);
            cp16(sBb + (uint32_t)((r * SPITCH + lch * 8) * 2),
                 Bg + (size_t)(n0 + r) * D_DIM + kk + lch * 8);
        }
    };

    float acc[4][4][4];
#pragma unroll
    for (int a = 0; a < 4; a++)
#pragma unroll
        for (int b = 0; b < 4; b++)
#pragma unroll
            for (int c = 0; c < 4; c++) acc[a][b][c] = 0.0f;

    load_step(0, 0);
    CP_COMMIT();

    for (int cur = 0; cur < 24; cur++) {
        CP_WAIT(0);
        __syncthreads();
        if (cur + 1 < 24) {
            load_step(cur + 1, (cur + 1) & 1);
            CP_COMMIT();
        }
        const uint32_t sAu = smem_u32 + (uint32_t)((cur & 1) * 2 * STAGE_BYTES);
        const uint32_t sBu = sAu + STAGE_BYTES;
#pragma unroll
        for (int ks = 0; ks < 4; ks++) {
            uint32_t bfr[4][2];
            {
                uint32_t t0[4], t1[4];
                ldsm_x4(t0, sBu + boff[0] + ks * 32);
                ldsm_x4(t1, sBu + boff[1] + ks * 32);
                bfr[0][0] = t0[0]; bfr[0][1] = t0[1];
                bfr[1][0] = t0[2]; bfr[1][1] = t0[3];
                bfr[2][0] = t1[0]; bfr[2][1] = t1[1];
                bfr[3][0] = t1[2]; bfr[3][1] = t1[3];
            }
#pragma unroll
            for (int mt = 0; mt < 4; mt++) {
                uint32_t afr[4];
                ldsm_x4(afr, sAu + aoff[mt] + ks * 32);
#pragma unroll
                for (int nn = 0; nn < 4; nn++)
                    mma16816(acc[mt][nn], afr, bfr[nn]);
            }
        }
    }

    float v1[8], v2[8]; int i1[8];
#pragma unroll
    for (int s = 0; s < 8; s++) { v1[s] = 3.4e38f; v2[s] = 3.4e38f; i1[s] = 0; }
#pragma unroll
    for (int mt = 0; mt < 4; mt++) {
#pragma unroll
        for (int nn = 0; nn < 4; nn++) {
            const int col = n0 + wn * 32 + nn * 8 + lr * 2;
            const float e0 = g_en[col], e1 = g_en[col + 1];
            const int s0 = mt * 2, s1 = mt * 2 + 1;
            UPD(s0, col,     e0 - 2.0f * acc[mt][nn][0]);
            UPD(s0, col + 1, e1 - 2.0f * acc[mt][nn][1]);
            UPD(s1, col,     e0 - 2.0f * acc[mt][nn][2]);
            UPD(s1, col + 1, e1 - 2.0f * acc[mt][nn][3]);
        }
    }

#pragma unroll
    for (int off = 1; off <= 2; off <<= 1) {
#pragma unroll
        for (int sl = 0; sl < 8; sl++) {
            float ov1 = __shfl_xor_sync(0xffffffffu, v1[sl], off);
            int   oi1 = __shfl_xor_sync(0xffffffffu, i1[sl], off);
            float ov2 = __shfl_xor_sync(0xffffffffu, v2[sl], off);
            if (ov1 < v1[sl] || (ov1 == v1[sl] && oi1 < i1[sl])) {
                v2[sl] = fminf(v1[sl], ov2); v1[sl] = ov1; i1[sl] = oi1;
            } else {
                v2[sl] = fminf(v2[sl], ov1);
            }
        }
    }

    __syncthreads();
    float* rv1 = (float*)dsm;
    int*   ri1 = (int*)(dsm + 2048);
    float* rv2 = (float*)(dsm + 4096);
    if (lr == 0) {
#pragma unroll
        for (int sl = 0; sl < 8; sl++) {
            int row = wm * 64 + (sl >> 1) * 16 + (sl & 1) * 8 + lq;
            rv1[row * 4 + wn] = v1[sl];
            ri1[row * 4 + wn] = i1[sl];
            rv2[row * 4 + wn] = v2[sl];
        }
    }
    __syncthreads();
    if (tid < 128) {
        float bv1 = rv1[tid * 4]; int bi1 = ri1[tid * 4]; float bv2 = rv2[tid * 4];
#pragma unroll
        for (int j = 1; j < 4; j++) {
            float ov1 = rv1[tid * 4 + j]; int oi1 = ri1[tid * 4 + j]; float ov2 = rv2[tid * 4 + j];
            if (ov1 < bv1 || (ov1 == bv1 && oi1 < bi1)) {
                bv2 = fminf(bv1, ov2); bv1 = ov1; bi1 = oi1;
            } else {
                bv2 = fminf(bv2, ov1);
            }
        }
        const int crow = f0 + tid;
        g_p2k[(size_t)crow * 16 + nt] =
            ((unsigned long long)fmap(bv1) << 32) | (unsigned)bi1;
        g_p2v[(size_t)crow * 16 + nt] = bv2;
    }
}

// ---------------------------------------------------------------------------
// combine: merge the 16 per-nt top-2s per flagged row -> final idx or exact flag
// ---------------------------------------------------------------------------
__global__ __launch_bounds__(256)
void combine_kernel()
{
    const int cnt = min(g_nflag1, MAXF);
    for (int f = blockIdx.x * 256 + threadIdx.x; f < cnt; f += gridDim.x * 256) {
        unsigned long long bestk = 0xFFFFFFFFFFFFFFFFull;
#pragma unroll
        for (int j = 0; j < 16; j++)
            bestk = min(bestk, g_p2k[(size_t)f * 16 + j]);
        float s1 = funmap((uint32_t)(bestk >> 32));
        float s2 = 3.4e38f;
#pragma unroll
        for (int j = 0; j < 16; j++) {
            unsigned long long k = g_p2k[(size_t)f * 16 + j];
            float v2 = g_p2v[(size_t)f * 16 + j];
            if (k != bestk) s2 = fminf(s2, funmap((uint32_t)(k >> 32)));
            s2 = fminf(s2, v2);
        }
        const int orig = g_flag1[f];
        if (s2 - s1 <= MARGIN2) {
            g_idx[orig]  = -1;
            g_best[orig] = 0xFFFFFFFFFFFFFFFFull;
            int slot = atomicAdd(&g_nflag, 1);
            g_flagged[slot] = orig;
        } else {
            g_idx[orig] = (int)(bestk & 0xFFFFFFFFull);
        }
    }
}

// ---------------------------------------------------------------------------
// Exact fp32 fallback for residual rows
// ---------------------------------------------------------------------------
__global__ __launch_bounds__(256)
void fallback_kernel(const float* __restrict__ emb)
{
    __shared__ float hrow[D_DIM];
    const int tid = threadIdx.x;
    const int cnt = g_nflag;
    const int total = cnt * 8;

    for (int wk = blockIdx.x; wk < total; wk += gridDim.x) {
        const int f     = wk >> 3;
        const int chunk = wk & 7;
        const int row   = g_flagged[f];

        if (tid < 128)
            *(float4*)(hrow + tid * 4) = *(const float4*)(g_h + (size_t)row * D_DIM + tid * 4);
        __syncthreads();

        const int k = chunk * 256 + tid;
        const float4* ep = (const float4*)(emb + (size_t)k * D_DIM);
        float a0 = 0.f, a1 = 0.f, a2 = 0.f, a3 = 0.f;
#pragma unroll 16
        for (int d4 = 0; d4 < D_DIM / 4; d4++) {
            float4 e = ep[d4];
            float4 h = *(const float4*)(hrow + d4 * 4);
            a0 += e.x * h.x; a1 += e.y * h.y; a2 += e.z * h.z; a3 += e.w * h.w;
        }
        float s = g_en[k] - 2.0f * ((a0 + a1) + (a2 + a3));
        unsigned long long key = ((unsigned long long)fmap(s) << 32) | (unsigned)k;
        atomicMin(&g_best[row], key);
        __syncthreads();
    }
}

// ---------------------------------------------------------------------------
// Epilogue per row
// ---------------------------------------------------------------------------
__global__ void epilogue_kernel(const float* __restrict__ emb, float* __restrict__ out)
{
    __shared__ float red[128];
    const int n   = blockIdx.x;
    const int tid = threadIdx.x;
    int idx = g_idx[n];
    if (idx < 0) idx = (int)(g_best[n] & 0xFFFFFFFFull);

    float4 hv = *(const float4*)(g_h + (size_t)n * D_DIM + tid * 4);
    float4 qv = *(const float4*)(emb + (size_t)idx * D_DIM + tid * 4);
    float d0 = qv.x - hv.x, d1 = qv.y - hv.y, d2 = qv.z - hv.z, d3 = qv.w - hv.w;

    float* qo = out + OFF_QOUT + (size_t)n * D_DIM + tid * 4;
    qo[0] = hv.x + d0; qo[1] = hv.y + d1; qo[2] = hv.z + d2; qo[3] = hv.w + d3;

    red[tid] = d0 * d0 + d1 * d1 + d2 * d2 + d3 * d3;

    float2* er2 = (float2*)(out + OFF_ENC + (size_t)n * K_CODES);
    const int unit = idx >> 1, comp = idx & 1;
#pragma unroll
    for (int i = 0; i < 8; i++) {
        int u = tid + i * 128;
        float2 v = make_float2(0.0f, 0.0f);
        if (u == unit) { if (comp == 0) v.x = 1.0f; else v.y = 1.0f; }
        er2[u] = v;
    }

    __syncthreads();
    for (int off = 64; off; off >>= 1) {
        if (tid < off) red[tid] += red[tid + off];
        __syncthreads();
    }
    if (tid == 0) {
        g_partial[n] = red[0];
        atomicAdd(&g_counts[idx], 1);
    }
}

// ---------------------------------------------------------------------------
__global__ void final_kernel(float* __restrict__ out)
{
    __shared__ float red[1024];
    const int tid = threadIdx.x;

    float s = 0.0f;
    for (int i = 0; i < N_ROWS / 1024; i++) s += g_partial[tid + i * 1024];
    red[tid] = s;
    __syncthreads();
    for (int off = 512; off; off >>= 1) {
        if (tid < off) red[tid] += red[tid + off];
        __syncthreads();
    }
    if (tid == 0) out[0] = 0.25f * red[0] / (float)((size_t)N_ROWS * D_DIM);
    __syncthreads();

    float p = 0.0f;
    for (int i = 0; i < K_CODES / 1024; i++) {
        float c  = (float)g_counts[tid + i * 1024];
        float pr = c * (1.0f / (float)N_ROWS);
        p += pr * logf(pr + 1e-10f);
    }
    red[tid] = p;
    __syncthreads();
    for (int off = 512; off; off >>= 1) {
        if (tid < off) red[tid] += red[tid + off];
        __syncthreads();
    }
    if (tid == 0) out[OFF_PERP] = expf(-red[0]);
}

// ---------------------------------------------------------------------------
extern "C" void kernel_launch(void* const* d_in, const int* in_sizes, int n_in,
                              void* d_out, int out_size)
{
    const float *x0 = nullptr, *x1 = nullptr, *W = nullptr, *b = nullptr, *emb = nullptr;
    for (int i = 0; i < n_in; i++) {
        const float* p = (const float*)d_in[i];
        const long long s = in_sizes[i];
        if (s == (long long)N_ROWS * HALFW)       { if (!x0) x0 = p; else x1 = p; }
        else if (s == (long long)D_DIM * D_DIM)   W = p;
        else if (s == (long long)D_DIM)           b = p;
        else if (s == (long long)K_CODES * D_DIM) emb = p;
    }
    float* out = (float*)d_out;

    static int smem_set = 0;
    if (!smem_set) {
        cudaFuncSetAttribute(gemm1_mma_kernel,
                             cudaFuncAttributeMaxDynamicSharedMemorySize, 4 * STAGE_BYTES);
        cudaFuncSetAttribute(gemm2_pass1_kernel,
                             cudaFuncAttributeMaxDynamicSharedMemorySize, 4 * STAGE_BYTES);
        cudaFuncSetAttribute(gemm2_pass2_kernel,
                             cudaFuncAttributeMaxDynamicSharedMemorySize, 4 * STAGE_BYTES);
        smem_set = 1;
    }

    prep_x_kernel<<<(N_ROWS * D_DIM) / 1024, 256>>>(x0, x1);
    prep_w_kernel<<<(D_DIM * D_DIM) / 1024, 256>>>(W);
    prep_emb_kernel<<<K_CODES, 128>>>(emb);
    gemm1_mma_kernel<<<dim3(D_DIM / 128, N_ROWS / 128), 256, 4 * STAGE_BYTES>>>(b);
    gemm2_pass1_kernel<<<N_ROWS / 128, 256, 4 * STAGE_BYTES>>>();
    gather_kernel<<<1024, 128>>>();
    gemm2_pass2_kernel<<<(MAXF / 128) * 16, 256, 4 * STAGE_BYTES>>>();
    combine_kernel<<<32, 256>>>();
    fallback_kernel<<<2048, 256>>>(emb);
    epilogue_kernel<<<N_ROWS, 128>>>(emb, out);
    final_kernel<<<1, 1024>>>(out);
}